// round 8
// baseline (speedup 1.0000x reference)
#include <cuda_runtime.h>
#include <cuda_bf16.h>
#include <math.h>
#include <stdint.h>

#define D 256
#define TT 4096
#define NB 4
#define BT (NB*TT)      // 16384 rows

// -------- scratch (allocation-free: __device__ globals) --------
__device__ __nv_bfloat16 g_xnb[BT * D];
__device__ __nv_bfloat16 g_qb[BT * D];
__device__ __nv_bfloat16 g_kb[BT * D];
__device__ __nv_bfloat16 g_vb[BT * D];
__device__ __nv_bfloat16 g_attnb[BT * D];
__device__ __nv_bfloat16 g_hnb[BT * D];
__device__ __nv_bfloat16 g_hb[BT * 4 * D];
__device__ __nv_bfloat16 g_wb[786432];   // bf16 weights: wq,wk,wv,wo,w1,w2

// ---------------- helpers ----------------
__device__ __forceinline__ void mma16(float* c, uint32_t a0, uint32_t a1,
                                      uint32_t a2, uint32_t a3,
                                      uint32_t b0, uint32_t b1) {
    asm volatile(
        "mma.sync.aligned.m16n8k16.row.col.f32.bf16.bf16.f32 "
        "{%0,%1,%2,%3}, {%4,%5,%6,%7}, {%8,%9}, {%0,%1,%2,%3};"
        : "+f"(c[0]), "+f"(c[1]), "+f"(c[2]), "+f"(c[3])
        : "r"(a0), "r"(a1), "r"(a2), "r"(a3), "r"(b0), "r"(b1));
}

__device__ __forceinline__ void ldm_x4(uint32_t& r0, uint32_t& r1,
                                       uint32_t& r2, uint32_t& r3, uint32_t addr) {
    asm volatile("ldmatrix.sync.aligned.m8n8.x4.shared.b16 {%0,%1,%2,%3}, [%4];"
                 : "=r"(r0), "=r"(r1), "=r"(r2), "=r"(r3) : "r"(addr));
}

__device__ __forceinline__ void ldm_x4t(uint32_t& r0, uint32_t& r1,
                                        uint32_t& r2, uint32_t& r3, uint32_t addr) {
    asm volatile("ldmatrix.sync.aligned.m8n8.x4.trans.shared.b16 {%0,%1,%2,%3}, [%4];"
                 : "=r"(r0), "=r"(r1), "=r"(r2), "=r"(r3) : "r"(addr));
}

__device__ __forceinline__ void cpa16(void* dst, const void* src) {
    uint32_t d = (uint32_t)__cvta_generic_to_shared(dst);
    asm volatile("cp.async.cg.shared.global [%0], [%1], 16;" :: "r"(d), "l"(src));
}
#define CP_COMMIT()  asm volatile("cp.async.commit_group;")
#define CP_WAIT(n)   asm volatile("cp.async.wait_group %0;" :: "n"(n) : "memory")

__device__ __forceinline__ uint32_t bf2u(__nv_bfloat162 h) {
    uint32_t u; *(__nv_bfloat162*)&u = h; return u;
}

__device__ __forceinline__ float gelu_exact(float x) {
    return 0.5f * x * (1.0f + erff(x * 0.70710678118654752440f));
}

// ---------------- weight bf16 pre-round ----------------
__global__ void convert_w(const float* __restrict__ wq, const float* __restrict__ wk,
                          const float* __restrict__ wv, const float* __restrict__ wo,
                          const float* __restrict__ w1, const float* __restrict__ w2,
                          __nv_bfloat16* __restrict__ dst) {
    size_t i = ((size_t)blockIdx.x * 256 + threadIdx.x) * 4;
    const float* src; size_t off = i;
    if      (i < 65536)  { src = wq; }
    else if (i < 131072) { src = wk; off = i - 65536; }
    else if (i < 196608) { src = wv; off = i - 131072; }
    else if (i < 262144) { src = wo; off = i - 196608; }
    else if (i < 524288) { src = w1; off = i - 262144; }
    else                 { src = w2; off = i - 524288; }
    float4 v = *(const float4*)(src + off);
    uint2 pk;
    pk.x = bf2u(__floats2bfloat162_rn(v.x, v.y));
    pk.y = bf2u(__floats2bfloat162_rn(v.z, v.w));
    *(uint2*)(dst + i) = pk;
}

// ---------------- RMSNorm (fp32 in, bf16 out), one warp per row ------------
__global__ void rmsnorm_kernel(const float* __restrict__ x,
                               const float* __restrict__ w,
                               __nv_bfloat16* __restrict__ out) {
    int row = blockIdx.x * 8 + (threadIdx.x >> 5);
    int lane = threadIdx.x & 31;
    const float* xr = x + (size_t)row * D + lane * 8;
    float4 a = *(const float4*)xr;
    float4 b = *(const float4*)(xr + 4);
    float ss = a.x*a.x + a.y*a.y + a.z*a.z + a.w*a.w
             + b.x*b.x + b.y*b.y + b.z*b.z + b.w*b.w;
    #pragma unroll
    for (int o = 16; o > 0; o >>= 1) ss += __shfl_xor_sync(0xffffffffu, ss, o);
    float r = rsqrtf(ss * (1.0f / D) + 1e-6f);
    float4 wa = *(const float4*)(w + lane * 8);
    float4 wb = *(const float4*)(w + lane * 8 + 4);
    uint4 pk;
    pk.x = bf2u(__floats2bfloat162_rn(a.x * r * wa.x, a.y * r * wa.y));
    pk.y = bf2u(__floats2bfloat162_rn(a.z * r * wa.z, a.w * r * wa.w));
    pk.z = bf2u(__floats2bfloat162_rn(b.x * r * wb.x, b.y * r * wb.y));
    pk.w = bf2u(__floats2bfloat162_rn(b.z * r * wb.z, b.w * r * wb.w));
    *(uint4*)(out + (size_t)row * D + lane * 8) = pk;
}

// ---------------- bf16 tensor-core GEMM: C = A[M,K] @ W[N,K]^T + bias ------
// block 128x128, 256 threads (8 warps 2x4), warp 64x32, k-chunk 32, double buf
template <int EPI>
__device__ __forceinline__ void
gemm_body(const __nv_bfloat16* __restrict__ A, const __nv_bfloat16* __restrict__ W,
          const float* __restrict__ bias, const float* __restrict__ res,
          void* __restrict__ Cv, int N, int K) {
    extern __shared__ __align__(16) __nv_bfloat16 smh[];   // 2 x (A 128x40 + B 128x40)
    const int tid = threadIdx.x, lane = tid & 31, wid = tid >> 5;
    const int wm = wid >> 2, wn = wid & 3;
    const int g = lane >> 2, t = lane & 3;
    const int bm = blockIdx.y * 128, bn = blockIdx.x * 128;

    float acc[4][4][4];
    #pragma unroll
    for (int mf = 0; mf < 4; mf++)
        #pragma unroll
        for (int nf = 0; nf < 4; nf++)
            #pragma unroll
            for (int q = 0; q < 4; q++) acc[mf][nf][q] = 0.f;

    #define GFILL(bufp, kt) do {                                              \
        __nv_bfloat16* sA_ = smh + (bufp) * 10240;                            \
        __nv_bfloat16* sB_ = sA_ + 5120;                                      \
        _Pragma("unroll")                                                     \
        for (int p = 0; p < 2; p++) {                                         \
            int i = tid + p * 256; int r = i >> 2; int c = (i & 3) * 8;       \
            cpa16(sA_ + r * 40 + c, A + (size_t)(bm + r) * K + (kt) + c);     \
            cpa16(sB_ + r * 40 + c, W + (size_t)(bn + r) * K + (kt) + c);     \
        }                                                                     \
        CP_COMMIT();                                                          \
    } while (0)

    GFILL(0, 0);
    int buf = 0;
    for (int kt = 0; kt < K; kt += 32) {
        if (kt + 32 < K) { GFILL(buf ^ 1, kt + 32); CP_WAIT(1); }
        else             { CP_WAIT(0); }
        __syncthreads();
        const __nv_bfloat16* sA = smh + buf * 10240;
        const __nv_bfloat16* sB = sA + 5120;
        #pragma unroll
        for (int ks = 0; ks < 2; ks++) {
            const int k0 = ks * 16 + 2 * t;
            uint32_t a[4][4], b[4][2];
            #pragma unroll
            for (int mf = 0; mf < 4; mf++) {
                const __nv_bfloat16* ap = sA + (wm * 64 + mf * 16 + g) * 40 + k0;
                a[mf][0] = *(const uint32_t*)ap;
                a[mf][1] = *(const uint32_t*)(ap + 8 * 40);
                a[mf][2] = *(const uint32_t*)(ap + 8);
                a[mf][3] = *(const uint32_t*)(ap + 8 * 40 + 8);
            }
            #pragma unroll
            for (int nf = 0; nf < 4; nf++) {
                const __nv_bfloat16* bp = sB + (wn * 32 + nf * 8 + g) * 40 + k0;
                b[nf][0] = *(const uint32_t*)bp;
                b[nf][1] = *(const uint32_t*)(bp + 8);
            }
            #pragma unroll
            for (int mf = 0; mf < 4; mf++)
                #pragma unroll
                for (int nf = 0; nf < 4; nf++)
                    mma16(acc[mf][nf], a[mf][0], a[mf][1], a[mf][2], a[mf][3],
                          b[nf][0], b[nf][1]);
        }
        __syncthreads();
        buf ^= 1;
    }
    #undef GFILL

    #pragma unroll
    for (int mf = 0; mf < 4; mf++) {
        #pragma unroll
        for (int nf = 0; nf < 4; nf++) {
            int row0 = bm + wm * 64 + mf * 16 + g;
            int col = bn + wn * 32 + nf * 8 + 2 * t;
            float2 bv = *(const float2*)&bias[col];
            #pragma unroll
            for (int h = 0; h < 2; h++) {
                int row = row0 + h * 8;
                float ox = acc[mf][nf][h * 2 + 0] + bv.x;
                float oy = acc[mf][nf][h * 2 + 1] + bv.y;
                if (EPI == 1) { ox = gelu_exact(ox); oy = gelu_exact(oy); }
                if (EPI == 2) {
                    float2 r2 = *(const float2*)(res + (size_t)row * N + col);
                    float2 o = make_float2(ox + r2.x, oy + r2.y);
                    *(float2*)((float*)Cv + (size_t)row * N + col) = o;
                } else {
                    *(uint32_t*)((__nv_bfloat16*)Cv + (size_t)row * N + col) =
                        bf2u(__floats2bfloat162_rn(ox, oy));
                }
            }
        }
    }
}

template <int EPI>
__global__ void __launch_bounds__(256, 2)
gemm_bf16(const __nv_bfloat16* __restrict__ A, const __nv_bfloat16* __restrict__ W,
          const float* __restrict__ bias, const float* __restrict__ res,
          void* __restrict__ Cv, int N, int K) {
    gemm_body<EPI>(A, W, bias, res, Cv, N, K);
}

__global__ void __launch_bounds__(256, 2)
gemm_qkv(const __nv_bfloat16* __restrict__ A, const __nv_bfloat16* __restrict__ wb,
         const float* __restrict__ bq, const float* __restrict__ bk,
         const float* __restrict__ bv,
         __nv_bfloat16* __restrict__ q, __nv_bfloat16* __restrict__ k,
         __nv_bfloat16* __restrict__ v) {
    int z = blockIdx.z;
    const __nv_bfloat16* W = wb + (size_t)z * 65536;
    const float* bias = (z == 0) ? bq : ((z == 1) ? bk : bv);
    __nv_bfloat16* C = (z == 0) ? q : ((z == 1) ? k : v);
    gemm_body<0>(A, W, bias, nullptr, C, 256, 256);
}

// ---------------- flash attention v2: warp-local softmax, P in registers ---
// BM=64 (4 warps x 16 q-rows), BN=64, D=256. 128 threads, 2 CTA/SM.
#define QKVS 264          // smem row stride in halves (528B)

__global__ void __launch_bounds__(128, 2)
flash_tc(const __nv_bfloat16* __restrict__ Q, const __nv_bfloat16* __restrict__ Kg,
         const __nv_bfloat16* __restrict__ Vg, __nv_bfloat16* __restrict__ O) {
    extern __shared__ __align__(16) __nv_bfloat16 smh[];
    __nv_bfloat16* sQ = smh;                 // 64 x 264
    __nv_bfloat16* sK = sQ + 64 * QKVS;      // 64 x 264 (reused as O staging)
    __nv_bfloat16* sV = sK + 64 * QKVS;      // 64 x 264

    const int tid = threadIdx.x, lane = tid & 31, wid = tid >> 5;
    const int g = lane >> 2, t = lane & 3;
    const int q0 = wid * 16;
    const int rA = q0 + g, rB = rA + 8;

    // qblk schedule: co-resident pairs sum to ~const work
    int id = blockIdx.x;
    int b = id & 3;
    int idx = id >> 2;
    int qblk = (idx < 32) ? (63 - 2 * idx) : (2 * (idx - 32));

    const size_t qbase = ((size_t)b * TT + (size_t)qblk * 64) * D;
    const size_t bbase = (size_t)b * TT * D;

    // prologue: Q + K(0), one group
    #pragma unroll
    for (int p = 0; p < 16; p++) {
        int i = tid + p * 128;
        int row = i >> 5, cv = i & 31;
        cpa16(sQ + row * QKVS + cv * 8, Q + qbase + (size_t)row * D + cv * 8);
        cpa16(sK + row * QKVS + cv * 8, Kg + bbase + (size_t)row * D + cv * 8);
    }
    CP_COMMIT();

    // ldmatrix lane addresses (bytes, shared space)
    const uint32_t sQa = (uint32_t)__cvta_generic_to_shared(sQ);
    const uint32_t sKa = (uint32_t)__cvta_generic_to_shared(sK);
    const uint32_t sVa = (uint32_t)__cvta_generic_to_shared(sV);
    const uint32_t qaddr = sQa + (((q0 + (lane & 15)) * QKVS) + (lane >> 4) * 8) * 2;
    const uint32_t kaddr = sKa + ((((lane & 7) + (lane >> 4) * 8) * QKVS)
                                  + ((lane >> 3) & 1) * 8) * 2;
    const uint32_t vaddr = sVa + (((((lane >> 4) & 1) * 8 + (lane & 7)) * QKVS)
                                  + ((lane >> 3) & 1) * 8) * 2;

    float oacc[32][4];
    #pragma unroll
    for (int nf = 0; nf < 32; nf++)
        #pragma unroll
        for (int q = 0; q < 4; q++) oacc[nf][q] = 0.f;

    float mA = -1e30f, mB = -1e30f, lA = 0.f, lB = 0.f;

    for (int j = 0; j <= qblk; j++) {
        __syncthreads();                       // PV(j-1) done reading sV
        {   // issue V(j)
            const __nv_bfloat16* vsrc = Vg + bbase + (size_t)j * 64 * D;
            #pragma unroll
            for (int p = 0; p < 16; p++) {
                int i = tid + p * 128;
                int row = i >> 5, cv = i & 31;
                cpa16(sV + row * QKVS + cv * 8, vsrc + (size_t)row * D + cv * 8);
            }
            CP_COMMIT();
        }
        CP_WAIT(1);                            // K(j) (and Q) arrived
        __syncthreads();

        // ---- S = Q K^T : warp-local 16x64 ----
        float s4[8][4];
        #pragma unroll
        for (int nf = 0; nf < 8; nf++)
            #pragma unroll
            for (int q = 0; q < 4; q++) s4[nf][q] = 0.f;

        #pragma unroll
        for (int ks = 0; ks < 16; ks++) {
            uint32_t qa0, qa1, qa2, qa3;
            ldm_x4(qa0, qa1, qa2, qa3, qaddr + ks * 32);
            #pragma unroll
            for (int np = 0; np < 4; np++) {
                uint32_t r0, r1, r2, r3;
                ldm_x4(r0, r1, r2, r3,
                       kaddr + (uint32_t)(np * 16 * QKVS) * 2 + ks * 32);
                mma16(s4[2 * np],     qa0, qa1, qa2, qa3, r0, r1);
                mma16(s4[2 * np + 1], qa0, qa1, qa2, qa3, r2, r3);
            }
        }
        #pragma unroll
        for (int nf = 0; nf < 8; nf++)
            #pragma unroll
            for (int q = 0; q < 4; q++) s4[nf][q] *= 0.0625f;

        if (j == qblk) {                       // causal mask (diag block)
            #pragma unroll
            for (int nf = 0; nf < 8; nf++) {
                int c0 = nf * 8 + 2 * t;
                if (c0 > rA)     s4[nf][0] = -1e30f;
                if (c0 + 1 > rA) s4[nf][1] = -1e30f;
                if (c0 > rB)     s4[nf][2] = -1e30f;
                if (c0 + 1 > rB) s4[nf][3] = -1e30f;
            }
        }

        // ---- warp-local online softmax ----
        float mxA = -1e30f, mxB = -1e30f;
        #pragma unroll
        for (int nf = 0; nf < 8; nf++) {
            mxA = fmaxf(mxA, fmaxf(s4[nf][0], s4[nf][1]));
            mxB = fmaxf(mxB, fmaxf(s4[nf][2], s4[nf][3]));
        }
        mxA = fmaxf(mxA, __shfl_xor_sync(0xffffffffu, mxA, 1));
        mxA = fmaxf(mxA, __shfl_xor_sync(0xffffffffu, mxA, 2));
        mxB = fmaxf(mxB, __shfl_xor_sync(0xffffffffu, mxB, 1));
        mxB = fmaxf(mxB, __shfl_xor_sync(0xffffffffu, mxB, 2));
        float nmA = fmaxf(mA, mxA), nmB = fmaxf(mB, mxB);
        float scA = __expf(mA - nmA), scB = __expf(mB - nmB);
        mA = nmA; mB = nmB;

        float sumA = 0.f, sumB = 0.f;
        uint32_t pa[4][4];
        #pragma unroll
        for (int nf = 0; nf < 8; nf++) {
            float p0 = __expf(s4[nf][0] - nmA);
            float p1 = __expf(s4[nf][1] - nmA);
            float p2 = __expf(s4[nf][2] - nmB);
            float p3 = __expf(s4[nf][3] - nmB);
            sumA += p0 + p1; sumB += p2 + p3;
            int sc = nf >> 1;
            if ((nf & 1) == 0) {
                pa[sc][0] = bf2u(__floats2bfloat162_rn(p0, p1));
                pa[sc][1] = bf2u(__floats2bfloat162_rn(p2, p3));
            } else {
                pa[sc][2] = bf2u(__floats2bfloat162_rn(p0, p1));
                pa[sc][3] = bf2u(__floats2bfloat162_rn(p2, p3));
            }
        }
        sumA += __shfl_xor_sync(0xffffffffu, sumA, 1);
        sumA += __shfl_xor_sync(0xffffffffu, sumA, 2);
        sumB += __shfl_xor_sync(0xffffffffu, sumB, 1);
        sumB += __shfl_xor_sync(0xffffffffu, sumB, 2);
        lA = lA * scA + sumA;
        lB = lB * scB + sumB;

        __syncthreads();                       // all warps done reading sK
        if (j < qblk) {                        // prefetch K(j+1)
            const __nv_bfloat16* ksrc = Kg + bbase + (size_t)(j + 1) * 64 * D;
            #pragma unroll
            for (int p = 0; p < 16; p++) {
                int i = tid + p * 128;
                int row = i >> 5, cv = i & 31;
                cpa16(sK + row * QKVS + cv * 8, ksrc + (size_t)row * D + cv * 8);
            }
            CP_COMMIT();
        }

        // rescale O (skip when warp-uniformly unchanged)
        if (!__all_sync(0xffffffffu, (scA == 1.f) & (scB == 1.f))) {
            #pragma unroll
            for (int nf = 0; nf < 32; nf++) {
                oacc[nf][0] *= scA; oacc[nf][1] *= scA;
                oacc[nf][2] *= scB; oacc[nf][3] *= scB;
            }
        }

        if (j < qblk) CP_WAIT(1); else CP_WAIT(0);   // V(j) ready
        __syncthreads();

        // ---- O += P V (warp: 16 q-rows x 256 d) ----
        #pragma unroll
        for (int sc = 0; sc < 4; sc++) {
            #pragma unroll
            for (int dp = 0; dp < 16; dp++) {
                uint32_t r0, r1, r2, r3;
                ldm_x4t(r0, r1, r2, r3,
                        vaddr + (uint32_t)(sc * 16 * QKVS + dp * 16) * 2);
                mma16(oacc[2 * dp],     pa[sc][0], pa[sc][1], pa[sc][2], pa[sc][3], r0, r2);
                mma16(oacc[2 * dp + 1], pa[sc][0], pa[sc][1], pa[sc][2], pa[sc][3], r1, r3);
            }
        }
    }

    // epilogue: normalize, stage in sK (dead), vectorized store
    __syncthreads();
    __nv_bfloat16* sO = sK;
    float invA = 1.0f / lA, invB = 1.0f / lB;
    #pragma unroll
    for (int nf = 0; nf < 32; nf++) {
        int col = nf * 8 + 2 * t;
        *(uint32_t*)(sO + rA * QKVS + col) =
            bf2u(__floats2bfloat162_rn(oacc[nf][0] * invA, oacc[nf][1] * invA));
        *(uint32_t*)(sO + rB * QKVS + col) =
            bf2u(__floats2bfloat162_rn(oacc[nf][2] * invB, oacc[nf][3] * invB));
    }
    __syncthreads();
    #pragma unroll
    for (int p = 0; p < 16; p++) {
        int i = tid + p * 128;
        int row = i >> 5, cv = i & 31;
        *(uint4*)(O + qbase + (size_t)row * D + cv * 8) =
            *(const uint4*)(sO + row * QKVS + cv * 8);
    }
}

// ---------------- launch ----------------
extern "C" void kernel_launch(void* const* d_in, const int* in_sizes, int n_in,
                              void* d_out, int out_size) {
    const float* x   = (const float*)d_in[0];
    const float* anw = (const float*)d_in[1];
    const float* mnw = (const float*)d_in[2];
    const float* wq  = (const float*)d_in[3];
    const float* bq  = (const float*)d_in[4];
    const float* wk  = (const float*)d_in[5];
    const float* bk  = (const float*)d_in[6];
    const float* wv  = (const float*)d_in[7];
    const float* bv  = (const float*)d_in[8];
    const float* wo  = (const float*)d_in[9];
    const float* bo  = (const float*)d_in[10];
    const float* w1  = (const float*)d_in[11];
    const float* b1  = (const float*)d_in[12];
    const float* w2  = (const float*)d_in[13];
    const float* b2  = (const float*)d_in[14];
    float* out = (float*)d_out;

    __nv_bfloat16 *xn, *q, *k, *v, *attn, *hn, *h, *wb;
    cudaGetSymbolAddress((void**)&xn,   g_xnb);
    cudaGetSymbolAddress((void**)&q,    g_qb);
    cudaGetSymbolAddress((void**)&k,    g_kb);
    cudaGetSymbolAddress((void**)&v,    g_vb);
    cudaGetSymbolAddress((void**)&attn, g_attnb);
    cudaGetSymbolAddress((void**)&hn,   g_hnb);
    cudaGetSymbolAddress((void**)&h,    g_hb);
    cudaGetSymbolAddress((void**)&wb,   g_wb);

    const int GEMM_SMEM  = 2 * 2 * 128 * 40 * 2;          // 40960
    const int FLASH_SMEM = 3 * 64 * QKVS * 2;             // 101376
    cudaFuncSetAttribute(flash_tc, cudaFuncAttributeMaxDynamicSharedMemorySize, FLASH_SMEM);

    // 0) round weights to bf16
    convert_w<<<768, 256>>>(wq, wk, wv, wo, w1, w2, wb);
    // 1) attn-norm -> bf16
    rmsnorm_kernel<<<BT / 8, 256>>>(x, anw, xn);
    // 2) fused q,k,v projections
    gemm_qkv<<<dim3(2, 128, 3), 256, GEMM_SMEM>>>(xn, wb, bq, bk, bv, q, k, v);
    // 3) causal attention
    flash_tc<<<256, 128, FLASH_SMEM>>>(q, k, v, attn);
    // 4) output projection + residual (fp32 out)
    gemm_bf16<2><<<dim3(2, 128), 256, GEMM_SMEM>>>(attn, wb + 196608, bo, x, out, 256, 256);
    // 5) mlp-norm -> bf16
    rmsnorm_kernel<<<BT / 8, 256>>>(out, mnw, hn);
    // 6) mlp up + gelu -> bf16
    gemm_bf16<1><<<dim3(8, 128), 256, GEMM_SMEM>>>(hn, wb + 262144, b1, nullptr, h, 1024, 256);
    // 7) mlp down + residual (in-place on out)
    gemm_bf16<2><<<dim3(2, 128), 256, GEMM_SMEM>>>(h, wb + 524288, b2, out, out, 256, 1024);
}

// round 9
// speedup vs baseline: 1.0296x; 1.0296x over previous
#include <cuda_runtime.h>
#include <cuda_bf16.h>
#include <math.h>
#include <stdint.h>

#define D 256
#define TT 4096
#define NB 4
#define BT (NB*TT)      // 16384 rows

// -------- scratch (allocation-free: __device__ globals) --------
__device__ __nv_bfloat16 g_xnb[BT * D];
__device__ __nv_bfloat16 g_qb[BT * D];
__device__ __nv_bfloat16 g_kb[BT * D];
__device__ __nv_bfloat16 g_vb[BT * D];
__device__ __nv_bfloat16 g_attnb[BT * D];
__device__ __nv_bfloat16 g_hnb[BT * D];
__device__ __nv_bfloat16 g_hb[BT * 4 * D];
__device__ __nv_bfloat16 g_wb[786432];   // bf16 weights: wq,wk,wv,wo,w1,w2

// ---------------- helpers ----------------
__device__ __forceinline__ void mma16(float* c, uint32_t a0, uint32_t a1,
                                      uint32_t a2, uint32_t a3,
                                      uint32_t b0, uint32_t b1) {
    asm volatile(
        "mma.sync.aligned.m16n8k16.row.col.f32.bf16.bf16.f32 "
        "{%0,%1,%2,%3}, {%4,%5,%6,%7}, {%8,%9}, {%0,%1,%2,%3};"
        : "+f"(c[0]), "+f"(c[1]), "+f"(c[2]), "+f"(c[3])
        : "r"(a0), "r"(a1), "r"(a2), "r"(a3), "r"(b0), "r"(b1));
}

__device__ __forceinline__ void ldm_x4(uint32_t& r0, uint32_t& r1,
                                       uint32_t& r2, uint32_t& r3, uint32_t addr) {
    asm volatile("ldmatrix.sync.aligned.m8n8.x4.shared.b16 {%0,%1,%2,%3}, [%4];"
                 : "=r"(r0), "=r"(r1), "=r"(r2), "=r"(r3) : "r"(addr));
}

__device__ __forceinline__ void ldm_x4t(uint32_t& r0, uint32_t& r1,
                                        uint32_t& r2, uint32_t& r3, uint32_t addr) {
    asm volatile("ldmatrix.sync.aligned.m8n8.x4.trans.shared.b16 {%0,%1,%2,%3}, [%4];"
                 : "=r"(r0), "=r"(r1), "=r"(r2), "=r"(r3) : "r"(addr));
}

__device__ __forceinline__ void cpa16(void* dst, const void* src) {
    uint32_t d = (uint32_t)__cvta_generic_to_shared(dst);
    asm volatile("cp.async.cg.shared.global [%0], [%1], 16;" :: "r"(d), "l"(src));
}
#define CP_COMMIT()  asm volatile("cp.async.commit_group;")
#define CP_WAIT(n)   asm volatile("cp.async.wait_group %0;" :: "n"(n) : "memory")

__device__ __forceinline__ uint32_t bf2u(__nv_bfloat162 h) {
    uint32_t u; *(__nv_bfloat162*)&u = h; return u;
}

__device__ __forceinline__ float gelu_exact(float x) {
    return 0.5f * x * (1.0f + erff(x * 0.70710678118654752440f));
}

// ---------------- weight bf16 pre-round ----------------
__global__ void convert_w(const float* __restrict__ wq, const float* __restrict__ wk,
                          const float* __restrict__ wv, const float* __restrict__ wo,
                          const float* __restrict__ w1, const float* __restrict__ w2,
                          __nv_bfloat16* __restrict__ dst) {
    size_t i = ((size_t)blockIdx.x * 256 + threadIdx.x) * 4;
    const float* src; size_t off = i;
    if      (i < 65536)  { src = wq; }
    else if (i < 131072) { src = wk; off = i - 65536; }
    else if (i < 196608) { src = wv; off = i - 131072; }
    else if (i < 262144) { src = wo; off = i - 196608; }
    else if (i < 524288) { src = w1; off = i - 262144; }
    else                 { src = w2; off = i - 524288; }
    float4 v = *(const float4*)(src + off);
    uint2 pk;
    pk.x = bf2u(__floats2bfloat162_rn(v.x, v.y));
    pk.y = bf2u(__floats2bfloat162_rn(v.z, v.w));
    *(uint2*)(dst + i) = pk;
}

// ---------------- RMSNorm (fp32 in, bf16 out), one warp per row ------------
__global__ void rmsnorm_kernel(const float* __restrict__ x,
                               const float* __restrict__ w,
                               __nv_bfloat16* __restrict__ out) {
    int row = blockIdx.x * 8 + (threadIdx.x >> 5);
    int lane = threadIdx.x & 31;
    const float* xr = x + (size_t)row * D + lane * 8;
    float4 a = *(const float4*)xr;
    float4 b = *(const float4*)(xr + 4);
    float ss = a.x*a.x + a.y*a.y + a.z*a.z + a.w*a.w
             + b.x*b.x + b.y*b.y + b.z*b.z + b.w*b.w;
    #pragma unroll
    for (int o = 16; o > 0; o >>= 1) ss += __shfl_xor_sync(0xffffffffu, ss, o);
    float r = rsqrtf(ss * (1.0f / D) + 1e-6f);
    float4 wa = *(const float4*)(w + lane * 8);
    float4 wb = *(const float4*)(w + lane * 8 + 4);
    uint4 pk;
    pk.x = bf2u(__floats2bfloat162_rn(a.x * r * wa.x, a.y * r * wa.y));
    pk.y = bf2u(__floats2bfloat162_rn(a.z * r * wa.z, a.w * r * wa.w));
    pk.z = bf2u(__floats2bfloat162_rn(b.x * r * wb.x, b.y * r * wb.y));
    pk.w = bf2u(__floats2bfloat162_rn(b.z * r * wb.z, b.w * r * wb.w));
    *(uint4*)(out + (size_t)row * D + lane * 8) = pk;
}

// ---------------- bf16 tensor-core GEMM: C = A[M,K] @ W[N,K]^T + bias ------
// block 128x128, 256 threads (8 warps 2x4), warp 64x32, k-chunk 32, double buf
template <int EPI>
__device__ __forceinline__ void
gemm_body(const __nv_bfloat16* __restrict__ A, const __nv_bfloat16* __restrict__ W,
          const float* __restrict__ bias, const float* __restrict__ res,
          void* __restrict__ Cv, int N, int K) {
    extern __shared__ __align__(16) __nv_bfloat16 smh[];   // 2 x (A 128x40 + B 128x40)
    const int tid = threadIdx.x, lane = tid & 31, wid = tid >> 5;
    const int wm = wid >> 2, wn = wid & 3;
    const int g = lane >> 2, t = lane & 3;
    const int bm = blockIdx.y * 128, bn = blockIdx.x * 128;

    float acc[4][4][4];
    #pragma unroll
    for (int mf = 0; mf < 4; mf++)
        #pragma unroll
        for (int nf = 0; nf < 4; nf++)
            #pragma unroll
            for (int q = 0; q < 4; q++) acc[mf][nf][q] = 0.f;

    #define GFILL(bufp, kt) do {                                              \
        __nv_bfloat16* sA_ = smh + (bufp) * 10240;                            \
        __nv_bfloat16* sB_ = sA_ + 5120;                                      \
        _Pragma("unroll")                                                     \
        for (int p = 0; p < 2; p++) {                                         \
            int i = tid + p * 256; int r = i >> 2; int c = (i & 3) * 8;       \
            cpa16(sA_ + r * 40 + c, A + (size_t)(bm + r) * K + (kt) + c);     \
            cpa16(sB_ + r * 40 + c, W + (size_t)(bn + r) * K + (kt) + c);     \
        }                                                                     \
        CP_COMMIT();                                                          \
    } while (0)

    GFILL(0, 0);
    int buf = 0;
    for (int kt = 0; kt < K; kt += 32) {
        if (kt + 32 < K) { GFILL(buf ^ 1, kt + 32); CP_WAIT(1); }
        else             { CP_WAIT(0); }
        __syncthreads();
        const __nv_bfloat16* sA = smh + buf * 10240;
        const __nv_bfloat16* sB = sA + 5120;
        #pragma unroll
        for (int ks = 0; ks < 2; ks++) {
            const int k0 = ks * 16 + 2 * t;
            uint32_t a[4][4], b[4][2];
            #pragma unroll
            for (int mf = 0; mf < 4; mf++) {
                const __nv_bfloat16* ap = sA + (wm * 64 + mf * 16 + g) * 40 + k0;
                a[mf][0] = *(const uint32_t*)ap;
                a[mf][1] = *(const uint32_t*)(ap + 8 * 40);
                a[mf][2] = *(const uint32_t*)(ap + 8);
                a[mf][3] = *(const uint32_t*)(ap + 8 * 40 + 8);
            }
            #pragma unroll
            for (int nf = 0; nf < 4; nf++) {
                const __nv_bfloat16* bp = sB + (wn * 32 + nf * 8 + g) * 40 + k0;
                b[nf][0] = *(const uint32_t*)bp;
                b[nf][1] = *(const uint32_t*)(bp + 8);
            }
            #pragma unroll
            for (int mf = 0; mf < 4; mf++)
                #pragma unroll
                for (int nf = 0; nf < 4; nf++)
                    mma16(acc[mf][nf], a[mf][0], a[mf][1], a[mf][2], a[mf][3],
                          b[nf][0], b[nf][1]);
        }
        __syncthreads();
        buf ^= 1;
    }
    #undef GFILL

    #pragma unroll
    for (int mf = 0; mf < 4; mf++) {
        #pragma unroll
        for (int nf = 0; nf < 4; nf++) {
            int row0 = bm + wm * 64 + mf * 16 + g;
            int col = bn + wn * 32 + nf * 8 + 2 * t;
            float2 bv = *(const float2*)&bias[col];
            #pragma unroll
            for (int h = 0; h < 2; h++) {
                int row = row0 + h * 8;
                float ox = acc[mf][nf][h * 2 + 0] + bv.x;
                float oy = acc[mf][nf][h * 2 + 1] + bv.y;
                if (EPI == 1) { ox = gelu_exact(ox); oy = gelu_exact(oy); }
                if (EPI == 2) {
                    float2 r2 = *(const float2*)(res + (size_t)row * N + col);
                    float2 o = make_float2(ox + r2.x, oy + r2.y);
                    *(float2*)((float*)Cv + (size_t)row * N + col) = o;
                } else {
                    *(uint32_t*)((__nv_bfloat16*)Cv + (size_t)row * N + col) =
                        bf2u(__floats2bfloat162_rn(ox, oy));
                }
            }
        }
    }
}

template <int EPI>
__global__ void __launch_bounds__(256, 2)
gemm_bf16(const __nv_bfloat16* __restrict__ A, const __nv_bfloat16* __restrict__ W,
          const float* __restrict__ bias, const float* __restrict__ res,
          void* __restrict__ Cv, int N, int K) {
    gemm_body<EPI>(A, W, bias, res, Cv, N, K);
}

__global__ void __launch_bounds__(256, 2)
gemm_qkv(const __nv_bfloat16* __restrict__ A, const __nv_bfloat16* __restrict__ wb,
         const float* __restrict__ bq, const float* __restrict__ bk,
         const float* __restrict__ bv,
         __nv_bfloat16* __restrict__ q, __nv_bfloat16* __restrict__ k,
         __nv_bfloat16* __restrict__ v) {
    int z = blockIdx.z;
    const __nv_bfloat16* W = wb + (size_t)z * 65536;
    const float* bias = (z == 0) ? bq : ((z == 1) ? bk : bv);
    __nv_bfloat16* C = (z == 0) ? q : ((z == 1) ? k : v);
    gemm_body<0>(A, W, bias, nullptr, C, 256, 256);
}

// ---------------- flash attention: ldmatrix + single-exchange softmax ------
// BM=BN=64, D=256. 8 warps (wm 0..3 q-groups, wn 0..1 s-halves). 2 CTA/SM.
#define QKVS 264          // smem row stride in halves (528B)
#define PSH  72

__global__ void __launch_bounds__(256, 2)
flash_tc(const __nv_bfloat16* __restrict__ Q, const __nv_bfloat16* __restrict__ Kg,
         const __nv_bfloat16* __restrict__ Vg, __nv_bfloat16* __restrict__ O) {
    extern __shared__ __align__(16) __nv_bfloat16 smh[];
    __nv_bfloat16* sQ = smh;                 // 64 x 264
    __nv_bfloat16* sK = sQ + 64 * QKVS;      // 64 x 264 (reused as O staging)
    __nv_bfloat16* sV = sK + 64 * QKVS;      // 64 x 264
    __nv_bfloat16* sP = sV + 64 * QKVS;      // 64 x 72
    __shared__ float sRmax[128], sRsum[128], sSc[64], sL[64];

    const int tid = threadIdx.x, lane = tid & 31, wid = tid >> 5;
    const int wm = wid >> 1, wn = wid & 1;
    const int g = lane >> 2, t = lane & 3;
    const int rA = wm * 16 + g, rB = rA + 8;

    // qblk schedule: co-resident pairs sum to ~const work
    int id = blockIdx.x;
    int b = id & 3;
    int idx = id >> 2;
    int qblk = (idx < 32) ? (63 - 2 * idx) : (2 * (idx - 32));

    const size_t qbase = ((size_t)b * TT + (size_t)qblk * 64) * D;
    const size_t bbase = (size_t)b * TT * D;

    // prologue: Q + K(0), one group
    #pragma unroll
    for (int p = 0; p < 8; p++) {
        int i = tid + p * 256;
        int row = i >> 5, cv = i & 31;
        cpa16(sQ + row * QKVS + cv * 8, Q + qbase + (size_t)row * D + cv * 8);
        cpa16(sK + row * QKVS + cv * 8, Kg + bbase + (size_t)row * D + cv * 8);
    }
    CP_COMMIT();

    // ldmatrix lane base addresses (bytes, shared space)
    const uint32_t sQa = (uint32_t)__cvta_generic_to_shared(sQ);
    const uint32_t sKa = (uint32_t)__cvta_generic_to_shared(sK);
    const uint32_t sVa = (uint32_t)__cvta_generic_to_shared(sV);
    const uint32_t sPa = (uint32_t)__cvta_generic_to_shared(sP);
    // A fragments of Q: rows wm*16 + (lane&15), col block (lane>>4)*8
    const uint32_t qaddr = sQa + (uint32_t)((wm * 16 + (lane & 15)) * QKVS
                                            + (lane >> 4) * 8) * 2;
    // B fragments of K: rows wn*32 + (lane&7) + (lane>>4)*8, col ((lane>>3)&1)*8
    const uint32_t kaddr = sKa + (uint32_t)((wn * 32 + (lane & 7) + (lane >> 4) * 8) * QKVS
                                            + ((lane >> 3) & 1) * 8) * 2;
    // B fragments of P^T: rows(q) wn*32 + (lane&7) + (lane>>4)*8, col ((lane>>3)&1)*8
    const uint32_t paddr = sPa + (uint32_t)((wn * 32 + (lane & 7) + (lane >> 4) * 8) * PSH
                                            + ((lane >> 3) & 1) * 8) * 2;
    // A fragments of V^T (trans): base for wm's 64 d-cols
    const uint32_t vaddr = sVa + (uint32_t)((((lane >> 4) & 1) * 8 + (lane & 7)) * QKVS
                                            + wm * 64 + ((lane >> 3) & 1) * 8) * 2;

    float oacc[4][4][4];
    #pragma unroll
    for (int mf = 0; mf < 4; mf++)
        #pragma unroll
        for (int nf = 0; nf < 4; nf++)
            #pragma unroll
            for (int q = 0; q < 4; q++) oacc[mf][nf][q] = 0.f;

    float mA = -1e30f, mB = -1e30f, lA = 0.f, lB = 0.f;

    for (int j = 0; j <= qblk; j++) {
        __syncthreads();                       // A: PV(j-1) done with sV, sP
        {   // issue V(j)
            const __nv_bfloat16* vsrc = Vg + bbase + (size_t)j * 64 * D;
            #pragma unroll
            for (int p = 0; p < 8; p++) {
                int i = tid + p * 256;
                int row = i >> 5, cv = i & 31;
                cpa16(sV + row * QKVS + cv * 8, vsrc + (size_t)row * D + cv * 8);
            }
            CP_COMMIT();
        }
        CP_WAIT(1);                            // K(j) (and Q) arrived
        __syncthreads();                       // B

        // ---- S = Q K^T : warp 16q x 32s ----
        float s4[4][4];
        #pragma unroll
        for (int nf = 0; nf < 4; nf++)
            #pragma unroll
            for (int q = 0; q < 4; q++) s4[nf][q] = 0.f;

        #pragma unroll
        for (int ks = 0; ks < 16; ks++) {
            uint32_t qa0, qa1, qa2, qa3;
            ldm_x4(qa0, qa1, qa2, qa3, qaddr + ks * 32);
            #pragma unroll
            for (int np = 0; np < 2; np++) {
                uint32_t r0, r1, r2, r3;
                ldm_x4(r0, r1, r2, r3,
                       kaddr + (uint32_t)(np * 16 * QKVS) * 2 + ks * 32);
                mma16(s4[2 * np],     qa0, qa1, qa2, qa3, r0, r1);
                mma16(s4[2 * np + 1], qa0, qa1, qa2, qa3, r2, r3);
            }
        }

        if (j == qblk) {                       // causal mask (raw domain)
            #pragma unroll
            for (int nf = 0; nf < 4; nf++) {
                int c0 = wn * 32 + nf * 8 + 2 * t;
                if (c0 > rA)     s4[nf][0] = -1e30f;
                if (c0 + 1 > rA) s4[nf][1] = -1e30f;
                if (c0 > rB)     s4[nf][2] = -1e30f;
                if (c0 + 1 > rB) s4[nf][3] = -1e30f;
            }
        }

        // ---- local (half-row) max, exp vs local max, local sum ----
        float mxA = -1e30f, mxB = -1e30f;
        #pragma unroll
        for (int nf = 0; nf < 4; nf++) {
            mxA = fmaxf(mxA, fmaxf(s4[nf][0], s4[nf][1]));
            mxB = fmaxf(mxB, fmaxf(s4[nf][2], s4[nf][3]));
        }
        mxA = fmaxf(mxA, __shfl_xor_sync(0xffffffffu, mxA, 1));
        mxA = fmaxf(mxA, __shfl_xor_sync(0xffffffffu, mxA, 2));
        mxB = fmaxf(mxB, __shfl_xor_sync(0xffffffffu, mxB, 1));
        mxB = fmaxf(mxB, __shfl_xor_sync(0xffffffffu, mxB, 2));
        const float msA = mxA * 0.0625f, msB = mxB * 0.0625f;  // scaled domain

        float sumA = 0.f, sumB = 0.f;
        #pragma unroll
        for (int nf = 0; nf < 4; nf++) {
            float p0 = __expf(fmaf(s4[nf][0], 0.0625f, -msA));
            float p1 = __expf(fmaf(s4[nf][1], 0.0625f, -msA));
            float p2 = __expf(fmaf(s4[nf][2], 0.0625f, -msB));
            float p3 = __expf(fmaf(s4[nf][3], 0.0625f, -msB));
            s4[nf][0] = p0; s4[nf][1] = p1; s4[nf][2] = p2; s4[nf][3] = p3;
            sumA += p0 + p1; sumB += p2 + p3;
        }
        sumA += __shfl_xor_sync(0xffffffffu, sumA, 1);
        sumA += __shfl_xor_sync(0xffffffffu, sumA, 2);
        sumB += __shfl_xor_sync(0xffffffffu, sumB, 1);
        sumB += __shfl_xor_sync(0xffffffffu, sumB, 2);
        if (t == 0) {
            sRmax[wn * 64 + rA] = msA; sRmax[wn * 64 + rB] = msB;
            sRsum[wn * 64 + rA] = sumA; sRsum[wn * 64 + rB] = sumB;
        }
        __syncthreads();                       // C: stats ready, sK reads done

        // prefetch K(j+1) under combine + P pack
        if (j < qblk) {
            const __nv_bfloat16* ksrc = Kg + bbase + (size_t)(j + 1) * 64 * D;
            #pragma unroll
            for (int p = 0; p < 8; p++) {
                int i = tid + p * 256;
                int row = i >> 5, cv = i & 31;
                cpa16(sK + row * QKVS + cv * 8, ksrc + (size_t)row * D + cv * 8);
            }
            CP_COMMIT();
        }

        // ---- combine both halves analytically ----
        float m0 = sRmax[rA], m1 = sRmax[64 + rA];
        float nmA = fmaxf(mA, fmaxf(m0, m1));
        float scA = __expf(mA - nmA);
        lA = lA * scA + sRsum[rA] * __expf(m0 - nmA)
                      + sRsum[64 + rA] * __expf(m1 - nmA);
        float cfA = __expf(msA - nmA);
        mA = nmA;

        m0 = sRmax[rB]; m1 = sRmax[64 + rB];
        float nmB = fmaxf(mB, fmaxf(m0, m1));
        float scB = __expf(mB - nmB);
        lB = lB * scB + sRsum[rB] * __expf(m0 - nmB)
                      + sRsum[64 + rB] * __expf(m1 - nmB);
        float cfB = __expf(msB - nmB);
        mB = nmB;

        if (wn == 0 && t == 0) { sSc[rA] = scA; sSc[rB] = scB; }

        // pack P * cf -> smem (bf16)
        #pragma unroll
        for (int nf = 0; nf < 4; nf++) {
            int c0 = wn * 32 + nf * 8 + 2 * t;
            *(uint32_t*)(sP + rA * PSH + c0) =
                bf2u(__floats2bfloat162_rn(s4[nf][0] * cfA, s4[nf][1] * cfA));
            *(uint32_t*)(sP + rB * PSH + c0) =
                bf2u(__floats2bfloat162_rn(s4[nf][2] * cfB, s4[nf][3] * cfB));
        }

        if (j < qblk) CP_WAIT(1); else CP_WAIT(0);   // V(j) landed (K(j+1) pending)
        __syncthreads();                       // D: P + sSc + V visible

        // ---- rescale O accumulators (PV q-col layout) ----
        float scr[4][2];
        bool uni = true;
        #pragma unroll
        for (int nf = 0; nf < 4; nf++) {
            int qc = wn * 32 + nf * 8 + 2 * t;
            scr[nf][0] = sSc[qc]; scr[nf][1] = sSc[qc + 1];
            uni = uni && (scr[nf][0] == 1.f) && (scr[nf][1] == 1.f);
        }
        if (!__all_sync(0xffffffffu, uni)) {
            #pragma unroll
            for (int nf = 0; nf < 4; nf++)
                #pragma unroll
                for (int mf = 0; mf < 4; mf++) {
                    oacc[mf][nf][0] *= scr[nf][0]; oacc[mf][nf][1] *= scr[nf][1];
                    oacc[mf][nf][2] *= scr[nf][0]; oacc[mf][nf][3] *= scr[nf][1];
                }
        }

        // ---- O^T += V^T P^T (warp: 64 d-rows x 32 q-cols) ----
        #pragma unroll
        for (int sc = 0; sc < 4; sc++) {
            uint32_t bb[4][2];
            #pragma unroll
            for (int nq = 0; nq < 2; nq++)
                ldm_x4(bb[2 * nq][0], bb[2 * nq][1], bb[2 * nq + 1][0], bb[2 * nq + 1][1],
                       paddr + (uint32_t)(nq * 16 * PSH) * 2 + sc * 32);
            #pragma unroll
            for (int mf = 0; mf < 4; mf++) {
                uint32_t a0, a1, a2, a3;
                ldm_x4t(a0, a1, a2, a3,
                        vaddr + (uint32_t)(sc * 16 * QKVS + mf * 16) * 2);
                #pragma unroll
                for (int nf = 0; nf < 4; nf++)
                    mma16(oacc[mf][nf], a0, a1, a2, a3, bb[nf][0], bb[nf][1]);
            }
        }
    }

    // epilogue: publish l, normalize, stage in sK (dead), vectorized store
    __syncthreads();
    if (wn == 0 && t == 0) { sL[rA] = lA; sL[rB] = lB; }
    __syncthreads();
    __nv_bfloat16* sO = sK;
    #pragma unroll
    for (int nf = 0; nf < 4; nf++) {
        int qc = wn * 32 + nf * 8 + 2 * t;
        float inv0 = 1.0f / sL[qc], inv1 = 1.0f / sL[qc + 1];
        #pragma unroll
        for (int mf = 0; mf < 4; mf++) {
            int dl = wm * 64 + mf * 16 + g;
            sO[qc * QKVS + dl]           = __float2bfloat16(oacc[mf][nf][0] * inv0);
            sO[(qc + 1) * QKVS + dl]     = __float2bfloat16(oacc[mf][nf][1] * inv1);
            sO[qc * QKVS + dl + 8]       = __float2bfloat16(oacc[mf][nf][2] * inv0);
            sO[(qc + 1) * QKVS + dl + 8] = __float2bfloat16(oacc[mf][nf][3] * inv1);
        }
    }
    __syncthreads();
    #pragma unroll
    for (int p = 0; p < 8; p++) {
        int i = tid + p * 256;
        int row = i >> 5, cv = i & 31;
        *(uint4*)(O + qbase + (size_t)row * D + cv * 8) =
            *(const uint4*)(sO + row * QKVS + cv * 8);
    }
}

// ---------------- launch ----------------
extern "C" void kernel_launch(void* const* d_in, const int* in_sizes, int n_in,
                              void* d_out, int out_size) {
    const float* x   = (const float*)d_in[0];
    const float* anw = (const float*)d_in[1];
    const float* mnw = (const float*)d_in[2];
    const float* wq  = (const float*)d_in[3];
    const float* bq  = (const float*)d_in[4];
    const float* wk  = (const float*)d_in[5];
    const float* bk  = (const float*)d_in[6];
    const float* wv  = (const float*)d_in[7];
    const float* bv  = (const float*)d_in[8];
    const float* wo  = (const float*)d_in[9];
    const float* bo  = (const float*)d_in[10];
    const float* w1  = (const float*)d_in[11];
    const float* b1  = (const float*)d_in[12];
    const float* w2  = (const float*)d_in[13];
    const float* b2  = (const float*)d_in[14];
    float* out = (float*)d_out;

    __nv_bfloat16 *xn, *q, *k, *v, *attn, *hn, *h, *wb;
    cudaGetSymbolAddress((void**)&xn,   g_xnb);
    cudaGetSymbolAddress((void**)&q,    g_qb);
    cudaGetSymbolAddress((void**)&k,    g_kb);
    cudaGetSymbolAddress((void**)&v,    g_vb);
    cudaGetSymbolAddress((void**)&attn, g_attnb);
    cudaGetSymbolAddress((void**)&hn,   g_hnb);
    cudaGetSymbolAddress((void**)&h,    g_hb);
    cudaGetSymbolAddress((void**)&wb,   g_wb);

    const int GEMM_SMEM  = 2 * 2 * 128 * 40 * 2;                 // 40960
    const int FLASH_SMEM = (3 * 64 * QKVS + 64 * PSH) * 2;       // 110592
    cudaFuncSetAttribute(flash_tc, cudaFuncAttributeMaxDynamicSharedMemorySize, FLASH_SMEM);

    // 0) round weights to bf16
    convert_w<<<768, 256>>>(wq, wk, wv, wo, w1, w2, wb);
    // 1) attn-norm -> bf16
    rmsnorm_kernel<<<BT / 8, 256>>>(x, anw, xn);
    // 2) fused q,k,v projections
    gemm_qkv<<<dim3(2, 128, 3), 256, GEMM_SMEM>>>(xn, wb, bq, bk, bv, q, k, v);
    // 3) causal attention
    flash_tc<<<256, 256, FLASH_SMEM>>>(q, k, v, attn);
    // 4) output projection + residual (fp32 out)
    gemm_bf16<2><<<dim3(2, 128), 256, GEMM_SMEM>>>(attn, wb + 196608, bo, x, out, 256, 256);
    // 5) mlp-norm -> bf16
    rmsnorm_kernel<<<BT / 8, 256>>>(out, mnw, hn);
    // 6) mlp up + gelu -> bf16
    gemm_bf16<1><<<dim3(8, 128), 256, GEMM_SMEM>>>(hn, wb + 262144, b1, nullptr, h, 1024, 256);
    // 7) mlp down + residual (in-place on out)
    gemm_bf16<2><<<dim3(2, 128), 256, GEMM_SMEM>>>(h, wb + 524288, b2, out, out, 256, 1024);
}

// round 13
// speedup vs baseline: 1.1346x; 1.1019x over previous
#include <cuda_runtime.h>
#include <cuda_bf16.h>
#include <math.h>
#include <stdint.h>

#define D 256
#define TT 4096
#define NB 4
#define BT (NB*TT)      // 16384 rows

// -------- scratch (allocation-free: __device__ globals) --------
__device__ __nv_bfloat16 g_xnb[BT * D];
__device__ __nv_bfloat16 g_qb[BT * D];
__device__ __nv_bfloat16 g_kb[BT * D];
__device__ __nv_bfloat16 g_vb[BT * D];
__device__ __nv_bfloat16 g_attnb[BT * D];
__device__ __nv_bfloat16 g_hnb[BT * D];
__device__ __nv_bfloat16 g_hb[BT * 4 * D];
__device__ __nv_bfloat16 g_wb[786432];   // bf16 weights: wq,wk,wv,wo,w1,w2
// split-KV partials: 640 units x 64 rows x 256 cols fp32 + per-row m,l
__device__ float g_pO[640 * 64 * 256];
__device__ float g_pM[640 * 64];
__device__ float g_pL[640 * 64];

// ---------------- helpers ----------------
__device__ __forceinline__ uint32_t smem_u32(const void* p) {
    return (uint32_t)__cvta_generic_to_shared(p);
}

__device__ __forceinline__ void mma16(float* c, uint32_t a0, uint32_t a1,
                                      uint32_t a2, uint32_t a3,
                                      uint32_t b0, uint32_t b1) {
    asm volatile(
        "mma.sync.aligned.m16n8k16.row.col.f32.bf16.bf16.f32 "
        "{%0,%1,%2,%3}, {%4,%5,%6,%7}, {%8,%9}, {%0,%1,%2,%3};"
        : "+f"(c[0]), "+f"(c[1]), "+f"(c[2]), "+f"(c[3])
        : "r"(a0), "r"(a1), "r"(a2), "r"(a3), "r"(b0), "r"(b1));
}

__device__ __forceinline__ void ldm_x4(uint32_t& r0, uint32_t& r1,
                                       uint32_t& r2, uint32_t& r3, uint32_t addr) {
    asm volatile("ldmatrix.sync.aligned.m8n8.x4.shared.b16 {%0,%1,%2,%3}, [%4];"
                 : "=r"(r0), "=r"(r1), "=r"(r2), "=r"(r3) : "r"(addr));
}

__device__ __forceinline__ void ldm_x4t(uint32_t& r0, uint32_t& r1,
                                        uint32_t& r2, uint32_t& r3, uint32_t addr) {
    asm volatile("ldmatrix.sync.aligned.m8n8.x4.trans.shared.b16 {%0,%1,%2,%3}, [%4];"
                 : "=r"(r0), "=r"(r1), "=r"(r2), "=r"(r3) : "r"(addr));
}

__device__ __forceinline__ void cpa16(void* dst, const void* src) {
    asm volatile("cp.async.cg.shared.global [%0], [%1], 16;"
                 :: "r"(smem_u32(dst)), "l"(src));
}
#define CP_COMMIT()  asm volatile("cp.async.commit_group;")
#define CP_WAIT(n)   asm volatile("cp.async.wait_group %0;" :: "n"(n) : "memory")

__device__ __forceinline__ uint32_t bf2u(__nv_bfloat162 h) {
    uint32_t u; *(__nv_bfloat162*)&u = h; return u;
}

__device__ __forceinline__ float gelu_exact(float x) {
    return 0.5f * x * (1.0f + erff(x * 0.70710678118654752440f));
}

// ---------------- weight bf16 pre-round ----------------
__global__ void convert_w(const float* __restrict__ wq, const float* __restrict__ wk,
                          const float* __restrict__ wv, const float* __restrict__ wo,
                          const float* __restrict__ w1, const float* __restrict__ w2,
                          __nv_bfloat16* __restrict__ dst) {
    size_t i = ((size_t)blockIdx.x * 256 + threadIdx.x) * 4;
    const float* src; size_t off = i;
    if      (i < 65536)  { src = wq; }
    else if (i < 131072) { src = wk; off = i - 65536; }
    else if (i < 196608) { src = wv; off = i - 131072; }
    else if (i < 262144) { src = wo; off = i - 196608; }
    else if (i < 524288) { src = w1; off = i - 262144; }
    else                 { src = w2; off = i - 524288; }
    float4 v = *(const float4*)(src + off);
    uint2 pk;
    pk.x = bf2u(__floats2bfloat162_rn(v.x, v.y));
    pk.y = bf2u(__floats2bfloat162_rn(v.z, v.w));
    *(uint2*)(dst + i) = pk;
}

// ---------------- RMSNorm (fp32 in, bf16 out), one warp per row ------------
__global__ void rmsnorm_kernel(const float* __restrict__ x,
                               const float* __restrict__ w,
                               __nv_bfloat16* __restrict__ out) {
    int row = blockIdx.x * 8 + (threadIdx.x >> 5);
    int lane = threadIdx.x & 31;
    const float* xr = x + (size_t)row * D + lane * 8;
    float4 a = *(const float4*)xr;
    float4 b = *(const float4*)(xr + 4);
    float ss = a.x*a.x + a.y*a.y + a.z*a.z + a.w*a.w
             + b.x*b.x + b.y*b.y + b.z*b.z + b.w*b.w;
    #pragma unroll
    for (int o = 16; o > 0; o >>= 1) ss += __shfl_xor_sync(0xffffffffu, ss, o);
    float r = rsqrtf(ss * (1.0f / D) + 1e-6f);
    float4 wa = *(const float4*)(w + lane * 8);
    float4 wb = *(const float4*)(w + lane * 8 + 4);
    uint4 pk;
    pk.x = bf2u(__floats2bfloat162_rn(a.x * r * wa.x, a.y * r * wa.y));
    pk.y = bf2u(__floats2bfloat162_rn(a.z * r * wa.z, a.w * r * wa.w));
    pk.z = bf2u(__floats2bfloat162_rn(b.x * r * wb.x, b.y * r * wb.y));
    pk.w = bf2u(__floats2bfloat162_rn(b.z * r * wb.z, b.w * r * wb.w));
    *(uint4*)(out + (size_t)row * D + lane * 8) = pk;
}

// ---------------- bf16 tensor-core GEMM: C = A[M,K] @ W[N,K]^T + bias ------
// block 128x128, 256 threads (8 warps 2x4), warp 64x32, k-chunk 32, double buf
template <int EPI>
__device__ __forceinline__ void
gemm_body(const __nv_bfloat16* __restrict__ A, const __nv_bfloat16* __restrict__ W,
          const float* __restrict__ bias, const float* __restrict__ res,
          void* __restrict__ Cv, int N, int K) {
    extern __shared__ __align__(16) __nv_bfloat16 smh[];   // 2 x (A 128x40 + B 128x40)
    const int tid = threadIdx.x, lane = tid & 31, wid = tid >> 5;
    const int wm = wid >> 2, wn = wid & 3;
    const int g = lane >> 2, t = lane & 3;
    const int bm = blockIdx.y * 128, bn = blockIdx.x * 128;

    float acc[4][4][4];
    #pragma unroll
    for (int mf = 0; mf < 4; mf++)
        #pragma unroll
        for (int nf = 0; nf < 4; nf++)
            #pragma unroll
            for (int q = 0; q < 4; q++) acc[mf][nf][q] = 0.f;

    #define GFILL(bufp, kt) do {                                              \
        __nv_bfloat16* sA_ = smh + (bufp) * 10240;                            \
        __nv_bfloat16* sB_ = sA_ + 5120;                                      \
        _Pragma("unroll")                                                     \
        for (int p = 0; p < 2; p++) {                                         \
            int i = tid + p * 256; int r = i >> 2; int c = (i & 3) * 8;       \
            cpa16(sA_ + r * 40 + c, A + (size_t)(bm + r) * K + (kt) + c);     \
            cpa16(sB_ + r * 40 + c, W + (size_t)(bn + r) * K + (kt) + c);     \
        }                                                                     \
        CP_COMMIT();                                                          \
    } while (0)

    GFILL(0, 0);
    int buf = 0;
    for (int kt = 0; kt < K; kt += 32) {
        if (kt + 32 < K) { GFILL(buf ^ 1, kt + 32); CP_WAIT(1); }
        else             { CP_WAIT(0); }
        __syncthreads();
        const __nv_bfloat16* sA = smh + buf * 10240;
        const __nv_bfloat16* sB = sA + 5120;
        #pragma unroll
        for (int ks = 0; ks < 2; ks++) {
            const int k0 = ks * 16 + 2 * t;
            uint32_t a[4][4], b[4][2];
            #pragma unroll
            for (int mf = 0; mf < 4; mf++) {
                const __nv_bfloat16* ap = sA + (wm * 64 + mf * 16 + g) * 40 + k0;
                a[mf][0] = *(const uint32_t*)ap;
                a[mf][1] = *(const uint32_t*)(ap + 8 * 40);
                a[mf][2] = *(const uint32_t*)(ap + 8);
                a[mf][3] = *(const uint32_t*)(ap + 8 * 40 + 8);
            }
            #pragma unroll
            for (int nf = 0; nf < 4; nf++) {
                const __nv_bfloat16* bp = sB + (wn * 32 + nf * 8 + g) * 40 + k0;
                b[nf][0] = *(const uint32_t*)bp;
                b[nf][1] = *(const uint32_t*)(bp + 8);
            }
            #pragma unroll
            for (int mf = 0; mf < 4; mf++)
                #pragma unroll
                for (int nf = 0; nf < 4; nf++)
                    mma16(acc[mf][nf], a[mf][0], a[mf][1], a[mf][2], a[mf][3],
                          b[nf][0], b[nf][1]);
        }
        __syncthreads();
        buf ^= 1;
    }
    #undef GFILL

    #pragma unroll
    for (int mf = 0; mf < 4; mf++) {
        #pragma unroll
        for (int nf = 0; nf < 4; nf++) {
            int row0 = bm + wm * 64 + mf * 16 + g;
            int col = bn + wn * 32 + nf * 8 + 2 * t;
            float2 bv = *(const float2*)&bias[col];
            #pragma unroll
            for (int h = 0; h < 2; h++) {
                int row = row0 + h * 8;
                float ox = acc[mf][nf][h * 2 + 0] + bv.x;
                float oy = acc[mf][nf][h * 2 + 1] + bv.y;
                if (EPI == 1) { ox = gelu_exact(ox); oy = gelu_exact(oy); }
                if (EPI == 2) {
                    float2 r2 = *(const float2*)(res + (size_t)row * N + col);
                    float2 o = make_float2(ox + r2.x, oy + r2.y);
                    *(float2*)((float*)Cv + (size_t)row * N + col) = o;
                } else {
                    *(uint32_t*)((__nv_bfloat16*)Cv + (size_t)row * N + col) =
                        bf2u(__floats2bfloat162_rn(ox, oy));
                }
            }
        }
    }
}

template <int EPI>
__global__ void __launch_bounds__(256, 2)
gemm_bf16(const __nv_bfloat16* __restrict__ A, const __nv_bfloat16* __restrict__ W,
          const float* __restrict__ bias, const float* __restrict__ res,
          void* __restrict__ Cv, int N, int K) {
    gemm_body<EPI>(A, W, bias, res, Cv, N, K);
}

__global__ void __launch_bounds__(256, 2)
gemm_qkv(const __nv_bfloat16* __restrict__ A, const __nv_bfloat16* __restrict__ wb,
         const float* __restrict__ bq, const float* __restrict__ bk,
         const float* __restrict__ bv,
         __nv_bfloat16* __restrict__ q, __nv_bfloat16* __restrict__ k,
         __nv_bfloat16* __restrict__ v) {
    int z = blockIdx.z;
    const __nv_bfloat16* W = wb + (size_t)z * 65536;
    const float* bias = (z == 0) ? bq : ((z == 1) ? bk : bv);
    __nv_bfloat16* C = (z == 0) ? q : ((z == 1) ? k : v);
    gemm_body<0>(A, W, bias, nullptr, C, 256, 256);
}

// ---------------- split-KV flash attention ---------------------------------
// 640 units: q-block (64 rows) x KV chunk (<=16 k-blocks). Heavy-first order:
//   qblk 63..48 (4 chunks): ids   0..255
//   qblk 47..32 (3 chunks): ids 256..447
//   qblk 31..16 (2 chunks): ids 448..575
//   qblk 15..0  (1 chunk):  ids 576..639  (writes final bf16 directly)
#define QKVS 264          // smem row stride in halves (528B)
#define PSH  72
#define KVC  16           // k-blocks per chunk

__global__ void __launch_bounds__(256, 2)
flash_tc(const __nv_bfloat16* __restrict__ Q, const __nv_bfloat16* __restrict__ Kg,
         const __nv_bfloat16* __restrict__ Vg, __nv_bfloat16* __restrict__ O,
         float* __restrict__ pO, float* __restrict__ pM, float* __restrict__ pL) {
    extern __shared__ __align__(16) __nv_bfloat16 smh[];
    __nv_bfloat16* sQ = smh;                 // 64 x 264
    __nv_bfloat16* sK = sQ + 64 * QKVS;      // 64 x 264 (reused for O staging)
    __nv_bfloat16* sV = sK + 64 * QKVS;      // 64 x 264
    __nv_bfloat16* sP = sV + 64 * QKVS;      // 64 x 72
    __shared__ float sRmax[128], sRsum[128], sSc[64], sL[64];

    const int tid = threadIdx.x, lane = tid & 31, wid = tid >> 5;
    const int wm = wid >> 1, wn = wid & 1;
    const int g = lane >> 2, t = lane & 3;
    const int rA = wm * 16 + g, rB = rA + 8;

    // ---- decode unit id -> (qblk, batch, chunk) ----
    const int id = blockIdx.x;
    int qblk, b, c, nc;
    if (id < 256)      { nc = 4; qblk = 63 - (id >> 4); int r = id & 15; b = r >> 2; c = r & 3; }
    else if (id < 448) { nc = 3; int u = id - 256; qblk = 47 - u / 12; int r = u % 12; b = r / 3; c = r % 3; }
    else if (id < 576) { nc = 2; int u = id - 448; qblk = 31 - (u >> 3); int r = u & 7; b = r >> 1; c = r & 1; }
    else               { nc = 1; int u = id - 576; qblk = 15 - (u >> 2); b = u & 3; c = 0; }
    const int j0 = c * KVC;
    const int j1 = min(j0 + KVC, qblk + 1);

    const size_t qbase = ((size_t)b * TT + (size_t)qblk * 64) * D;
    const size_t bbase = (size_t)b * TT * D;

    // prologue: Q + K(j0), one group
    #pragma unroll
    for (int p = 0; p < 8; p++) {
        int i = tid + p * 256;
        int row = i >> 5, cv = i & 31;
        cpa16(sQ + row * QKVS + cv * 8, Q + qbase + (size_t)row * D + cv * 8);
        cpa16(sK + row * QKVS + cv * 8,
              Kg + bbase + (size_t)j0 * 64 * D + (size_t)row * D + cv * 8);
    }
    CP_COMMIT();

    const uint32_t sQa = smem_u32(sQ);
    const uint32_t sKa = smem_u32(sK);
    const uint32_t sVa = smem_u32(sV);
    const uint32_t sPa = smem_u32(sP);
    const uint32_t qaddr = sQa + (uint32_t)((wm * 16 + (lane & 15)) * QKVS
                                            + (lane >> 4) * 8) * 2;
    const uint32_t kaddr = sKa + (uint32_t)((wn * 32 + (lane & 7) + (lane >> 4) * 8) * QKVS
                                            + ((lane >> 3) & 1) * 8) * 2;
    const uint32_t paddr = sPa + (uint32_t)((wn * 32 + (lane & 7) + (lane >> 4) * 8) * PSH
                                            + ((lane >> 3) & 1) * 8) * 2;
    const uint32_t vaddr = sVa + (uint32_t)((((lane >> 4) & 1) * 8 + (lane & 7)) * QKVS
                                            + wm * 64 + ((lane >> 3) & 1) * 8) * 2;

    float oacc[4][4][4];
    #pragma unroll
    for (int mf = 0; mf < 4; mf++)
        #pragma unroll
        for (int nf = 0; nf < 4; nf++)
            #pragma unroll
            for (int q = 0; q < 4; q++) oacc[mf][nf][q] = 0.f;

    float mA = -1e30f, mB = -1e30f, lA = 0.f, lB = 0.f;

    for (int j = j0; j < j1; j++) {
        __syncthreads();
        {
            const __nv_bfloat16* vsrc = Vg + bbase + (size_t)j * 64 * D;
            #pragma unroll
            for (int p = 0; p < 8; p++) {
                int i = tid + p * 256;
                int row = i >> 5, cv = i & 31;
                cpa16(sV + row * QKVS + cv * 8, vsrc + (size_t)row * D + cv * 8);
            }
            CP_COMMIT();
        }
        CP_WAIT(1);
        __syncthreads();

        float s4[4][4];
        #pragma unroll
        for (int nf = 0; nf < 4; nf++)
            #pragma unroll
            for (int q = 0; q < 4; q++) s4[nf][q] = 0.f;

        #pragma unroll
        for (int ks = 0; ks < 16; ks++) {
            uint32_t qa0, qa1, qa2, qa3;
            ldm_x4(qa0, qa1, qa2, qa3, qaddr + ks * 32);
            #pragma unroll
            for (int np = 0; np < 2; np++) {
                uint32_t r0, r1, r2, r3;
                ldm_x4(r0, r1, r2, r3,
                       kaddr + (uint32_t)(np * 16 * QKVS) * 2 + ks * 32);
                mma16(s4[2 * np],     qa0, qa1, qa2, qa3, r0, r1);
                mma16(s4[2 * np + 1], qa0, qa1, qa2, qa3, r2, r3);
            }
        }

        if (j == qblk) {                       // causal mask (diag block)
            #pragma unroll
            for (int nf = 0; nf < 4; nf++) {
                int c0 = wn * 32 + nf * 8 + 2 * t;
                if (c0 > rA)     s4[nf][0] = -1e30f;
                if (c0 + 1 > rA) s4[nf][1] = -1e30f;
                if (c0 > rB)     s4[nf][2] = -1e30f;
                if (c0 + 1 > rB) s4[nf][3] = -1e30f;
            }
        }

        float mxA = -1e30f, mxB = -1e30f;
        #pragma unroll
        for (int nf = 0; nf < 4; nf++) {
            mxA = fmaxf(mxA, fmaxf(s4[nf][0], s4[nf][1]));
            mxB = fmaxf(mxB, fmaxf(s4[nf][2], s4[nf][3]));
        }
        mxA = fmaxf(mxA, __shfl_xor_sync(0xffffffffu, mxA, 1));
        mxA = fmaxf(mxA, __shfl_xor_sync(0xffffffffu, mxA, 2));
        mxB = fmaxf(mxB, __shfl_xor_sync(0xffffffffu, mxB, 1));
        mxB = fmaxf(mxB, __shfl_xor_sync(0xffffffffu, mxB, 2));
        const float msA = mxA * 0.0625f, msB = mxB * 0.0625f;

        float sumA = 0.f, sumB = 0.f;
        #pragma unroll
        for (int nf = 0; nf < 4; nf++) {
            float p0 = __expf(fmaf(s4[nf][0], 0.0625f, -msA));
            float p1 = __expf(fmaf(s4[nf][1], 0.0625f, -msA));
            float p2 = __expf(fmaf(s4[nf][2], 0.0625f, -msB));
            float p3 = __expf(fmaf(s4[nf][3], 0.0625f, -msB));
            s4[nf][0] = p0; s4[nf][1] = p1; s4[nf][2] = p2; s4[nf][3] = p3;
            sumA += p0 + p1; sumB += p2 + p3;
        }
        sumA += __shfl_xor_sync(0xffffffffu, sumA, 1);
        sumA += __shfl_xor_sync(0xffffffffu, sumA, 2);
        sumB += __shfl_xor_sync(0xffffffffu, sumB, 1);
        sumB += __shfl_xor_sync(0xffffffffu, sumB, 2);
        if (t == 0) {
            sRmax[wn * 64 + rA] = msA; sRmax[wn * 64 + rB] = msB;
            sRsum[wn * 64 + rA] = sumA; sRsum[wn * 64 + rB] = sumB;
        }
        __syncthreads();

        if (j < j1 - 1) {
            const __nv_bfloat16* ksrc = Kg + bbase + (size_t)(j + 1) * 64 * D;
            #pragma unroll
            for (int p = 0; p < 8; p++) {
                int i = tid + p * 256;
                int row = i >> 5, cv = i & 31;
                cpa16(sK + row * QKVS + cv * 8, ksrc + (size_t)row * D + cv * 8);
            }
            CP_COMMIT();
        }

        float m0 = sRmax[rA], m1 = sRmax[64 + rA];
        float nmA = fmaxf(mA, fmaxf(m0, m1));
        float scA = __expf(mA - nmA);
        lA = lA * scA + sRsum[rA] * __expf(m0 - nmA)
                      + sRsum[64 + rA] * __expf(m1 - nmA);
        float cfA = __expf(msA - nmA);
        mA = nmA;

        m0 = sRmax[rB]; m1 = sRmax[64 + rB];
        float nmB = fmaxf(mB, fmaxf(m0, m1));
        float scB = __expf(mB - nmB);
        lB = lB * scB + sRsum[rB] * __expf(m0 - nmB)
                      + sRsum[64 + rB] * __expf(m1 - nmB);
        float cfB = __expf(msB - nmB);
        mB = nmB;

        if (wn == 0 && t == 0) { sSc[rA] = scA; sSc[rB] = scB; }

        #pragma unroll
        for (int nf = 0; nf < 4; nf++) {
            int c0 = wn * 32 + nf * 8 + 2 * t;
            *(uint32_t*)(sP + rA * PSH + c0) =
                bf2u(__floats2bfloat162_rn(s4[nf][0] * cfA, s4[nf][1] * cfA));
            *(uint32_t*)(sP + rB * PSH + c0) =
                bf2u(__floats2bfloat162_rn(s4[nf][2] * cfB, s4[nf][3] * cfB));
        }

        if (j < j1 - 1) CP_WAIT(1); else CP_WAIT(0);
        __syncthreads();

        float scr[4][2];
        bool uni = true;
        #pragma unroll
        for (int nf = 0; nf < 4; nf++) {
            int qc = wn * 32 + nf * 8 + 2 * t;
            scr[nf][0] = sSc[qc]; scr[nf][1] = sSc[qc + 1];
            uni = uni && (scr[nf][0] == 1.f) && (scr[nf][1] == 1.f);
        }
        if (!__all_sync(0xffffffffu, uni)) {
            #pragma unroll
            for (int nf = 0; nf < 4; nf++)
                #pragma unroll
                for (int mf = 0; mf < 4; mf++) {
                    oacc[mf][nf][0] *= scr[nf][0]; oacc[mf][nf][1] *= scr[nf][1];
                    oacc[mf][nf][2] *= scr[nf][0]; oacc[mf][nf][3] *= scr[nf][1];
                }
        }

        #pragma unroll
        for (int sc = 0; sc < 4; sc++) {
            uint32_t bb[4][2];
            #pragma unroll
            for (int nq = 0; nq < 2; nq++)
                ldm_x4(bb[2 * nq][0], bb[2 * nq][1], bb[2 * nq + 1][0], bb[2 * nq + 1][1],
                       paddr + (uint32_t)(nq * 16 * PSH) * 2 + sc * 32);
            #pragma unroll
            for (int mf = 0; mf < 4; mf++) {
                uint32_t a0, a1, a2, a3;
                ldm_x4t(a0, a1, a2, a3,
                        vaddr + (uint32_t)(sc * 16 * QKVS + mf * 16) * 2);
                #pragma unroll
                for (int nf = 0; nf < 4; nf++)
                    mma16(oacc[mf][nf], a0, a1, a2, a3, bb[nf][0], bb[nf][1]);
            }
        }
    }

    __syncthreads();   // PV done reading sK/sV; staging regions free
    if (nc == 1) {
        // final: normalize, bf16 out via sK staging
        if (wn == 0 && t == 0) { sL[rA] = lA; sL[rB] = lB; }
        __syncthreads();
        __nv_bfloat16* sO = sK;
        #pragma unroll
        for (int nf = 0; nf < 4; nf++) {
            int qc = wn * 32 + nf * 8 + 2 * t;
            float inv0 = 1.0f / sL[qc], inv1 = 1.0f / sL[qc + 1];
            #pragma unroll
            for (int mf = 0; mf < 4; mf++) {
                int dl = wm * 64 + mf * 16 + g;
                sO[qc * QKVS + dl]           = __float2bfloat16(oacc[mf][nf][0] * inv0);
                sO[(qc + 1) * QKVS + dl]     = __float2bfloat16(oacc[mf][nf][1] * inv1);
                sO[qc * QKVS + dl + 8]       = __float2bfloat16(oacc[mf][nf][2] * inv0);
                sO[(qc + 1) * QKVS + dl + 8] = __float2bfloat16(oacc[mf][nf][3] * inv1);
            }
        }
        __syncthreads();
        #pragma unroll
        for (int p = 0; p < 8; p++) {
            int i = tid + p * 256;
            int row = i >> 5, cv = i & 31;
            *(uint4*)(O + qbase + (size_t)row * D + cv * 8) =
                *(const uint4*)(sO + row * QKVS + cv * 8);
        }
    } else {
        // partial: unnormalized fp32 O + per-row m,l, staged through smem
        float* sOf = (float*)(smh + 64 * QKVS);    // 64 x 260 fp32 (over sK+sV)
        #pragma unroll
        for (int nf = 0; nf < 4; nf++) {
            int qc = wn * 32 + nf * 8 + 2 * t;
            #pragma unroll
            for (int mf = 0; mf < 4; mf++) {
                int dl = wm * 64 + mf * 16 + g;
                sOf[qc * 260 + dl]           = oacc[mf][nf][0];
                sOf[(qc + 1) * 260 + dl]     = oacc[mf][nf][1];
                sOf[qc * 260 + dl + 8]       = oacc[mf][nf][2];
                sOf[(qc + 1) * 260 + dl + 8] = oacc[mf][nf][3];
            }
        }
        if (wn == 0 && t == 0) {
            pM[id * 64 + rA] = mA; pM[id * 64 + rB] = mB;
            pL[id * 64 + rA] = lA; pL[id * 64 + rB] = lB;
        }
        __syncthreads();
        float* dst = pO + (size_t)id * 16384;
        #pragma unroll
        for (int p = 0; p < 16; p++) {
            int i = tid + p * 256;              // 0..4095 float4 slots
            int row = i >> 6, c4 = (i & 63) * 4;
            *(float4*)(dst + (size_t)row * 256 + c4) =
                *(const float4*)&sOf[row * 260 + c4];
        }
    }
}

// ---------------- combine partials (q-blocks with nc >= 2) -----------------
// grid 192: qblk = 16 + (bx>>2), b = bx&3. 256 threads: row = tid>>2, 64 cols.
__global__ void __launch_bounds__(256)
combine_kernel(const float* __restrict__ pO, const float* __restrict__ pM,
               const float* __restrict__ pL, __nv_bfloat16* __restrict__ O) {
    int qblk = 16 + (blockIdx.x >> 2);
    int b = blockIdx.x & 3;
    int nc = qblk / 16 + 1;
    int base;
    if      (qblk >= 48) base = (63 - qblk) * 16;
    else if (qblk >= 32) base = 256 + (47 - qblk) * 12;
    else                 base = 448 + (31 - qblk) * 8;

    int row = threadIdx.x >> 2;
    int cg = (threadIdx.x & 3) * 64;

    float macc = -1e30f, lacc = 0.f;
    float acc[64];
    #pragma unroll
    for (int i = 0; i < 64; i++) acc[i] = 0.f;

    for (int c = 0; c < nc; c++) {
        int u = base + b * nc + c;
        float mc = pM[u * 64 + row], lc = pL[u * 64 + row];
        float nm = fmaxf(macc, mc);
        float w0 = __expf(macc - nm), w1 = __expf(mc - nm);
        lacc = lacc * w0 + lc * w1;
        const float* src = pO + (size_t)u * 16384 + (size_t)row * 256 + cg;
        #pragma unroll
        for (int i = 0; i < 64; i += 4) {
            float4 v = *(const float4*)(src + i);
            acc[i + 0] = acc[i + 0] * w0 + v.x * w1;
            acc[i + 1] = acc[i + 1] * w0 + v.y * w1;
            acc[i + 2] = acc[i + 2] * w0 + v.z * w1;
            acc[i + 3] = acc[i + 3] * w0 + v.w * w1;
        }
        macc = nm;
    }

    float inv = 1.0f / lacc;
    __nv_bfloat16* dst = O + ((size_t)b * TT + (size_t)qblk * 64 + row) * 256 + cg;
    #pragma unroll
    for (int i = 0; i < 64; i += 8) {
        uint4 pk;
        pk.x = bf2u(__floats2bfloat162_rn(acc[i + 0] * inv, acc[i + 1] * inv));
        pk.y = bf2u(__floats2bfloat162_rn(acc[i + 2] * inv, acc[i + 3] * inv));
        pk.z = bf2u(__floats2bfloat162_rn(acc[i + 4] * inv, acc[i + 5] * inv));
        pk.w = bf2u(__floats2bfloat162_rn(acc[i + 6] * inv, acc[i + 7] * inv));
        *(uint4*)(dst + i) = pk;
    }
}

// ---------------- launch ----------------
extern "C" void kernel_launch(void* const* d_in, const int* in_sizes, int n_in,
                              void* d_out, int out_size) {
    const float* x   = (const float*)d_in[0];
    const float* anw = (const float*)d_in[1];
    const float* mnw = (const float*)d_in[2];
    const float* wq  = (const float*)d_in[3];
    const float* bq  = (const float*)d_in[4];
    const float* wk  = (const float*)d_in[5];
    const float* bk  = (const float*)d_in[6];
    const float* wv  = (const float*)d_in[7];
    const float* bv  = (const float*)d_in[8];
    const float* wo  = (const float*)d_in[9];
    const float* bo  = (const float*)d_in[10];
    const float* w1  = (const float*)d_in[11];
    const float* b1  = (const float*)d_in[12];
    const float* w2  = (const float*)d_in[13];
    const float* b2  = (const float*)d_in[14];
    float* out = (float*)d_out;

    __nv_bfloat16 *xn, *q, *k, *v, *attn, *hn, *h, *wb;
    float *pO, *pM, *pL;
    cudaGetSymbolAddress((void**)&xn,   g_xnb);
    cudaGetSymbolAddress((void**)&q,    g_qb);
    cudaGetSymbolAddress((void**)&k,    g_kb);
    cudaGetSymbolAddress((void**)&v,    g_vb);
    cudaGetSymbolAddress((void**)&attn, g_attnb);
    cudaGetSymbolAddress((void**)&hn,   g_hnb);
    cudaGetSymbolAddress((void**)&h,    g_hb);
    cudaGetSymbolAddress((void**)&wb,   g_wb);
    cudaGetSymbolAddress((void**)&pO,   g_pO);
    cudaGetSymbolAddress((void**)&pM,   g_pM);
    cudaGetSymbolAddress((void**)&pL,   g_pL);

    const int GEMM_SMEM  = 2 * 2 * 128 * 40 * 2;                 // 40960
    const int FLASH_SMEM = (3 * 64 * QKVS + 64 * PSH) * 2;       // 110592
    cudaFuncSetAttribute(flash_tc, cudaFuncAttributeMaxDynamicSharedMemorySize, FLASH_SMEM);

    // 0) round weights to bf16
    convert_w<<<768, 256>>>(wq, wk, wv, wo, w1, w2, wb);
    // 1) attn-norm -> bf16
    rmsnorm_kernel<<<BT / 8, 256>>>(x, anw, xn);
    // 2) fused q,k,v projections
    gemm_qkv<<<dim3(2, 128, 3), 256, GEMM_SMEM>>>(xn, wb, bq, bk, bv, q, k, v);
    // 3) causal attention: split-KV units + combine
    flash_tc<<<640, 256, FLASH_SMEM>>>(q, k, v, attn, pO, pM, pL);
    combine_kernel<<<192, 256>>>(pO, pM, pL, attn);
    // 4) output projection + residual (fp32 out)
    gemm_bf16<2><<<dim3(2, 128), 256, GEMM_SMEM>>>(attn, wb + 196608, bo, x, out, 256, 256);
    // 5) mlp-norm -> bf16
    rmsnorm_kernel<<<BT / 8, 256>>>(out, mnw, hn);
    // 6) mlp up + gelu -> bf16
    gemm_bf16<1><<<dim3(8, 128), 256, GEMM_SMEM>>>(hn, wb + 262144, b1, nullptr, h, 1024, 256);
    // 7) mlp down + residual (in-place on out)
    gemm_bf16<2><<<dim3(2, 128), 256, GEMM_SMEM>>>(h, wb + 524288, b2, out, out, 256, 1024);
}

// round 14
// speedup vs baseline: 1.2030x; 1.0603x over previous
#include <cuda_runtime.h>
#include <cuda_bf16.h>
#include <math.h>
#include <stdint.h>

#define D 256
#define TT 4096
#define NB 4
#define BT (NB*TT)      // 16384 rows

// -------- scratch (allocation-free: __device__ globals) --------
__device__ __nv_bfloat16 g_xnb[BT * D];
__device__ __nv_bfloat16 g_qb[BT * D];
__device__ __nv_bfloat16 g_kb[BT * D];
__device__ __nv_bfloat16 g_vb[BT * D];
__device__ __nv_bfloat16 g_attnb[BT * D];
__device__ __nv_bfloat16 g_hnb[BT * D];
__device__ __nv_bfloat16 g_hb[BT * 4 * D];
__device__ __nv_bfloat16 g_wb[786432];   // bf16 weights: wq,wk,wv,wo,w1,w2
// split-KV partials: 640 units x 64 rows x 256 cols fp32 + per-row m,l
__device__ float g_pO[640 * 64 * 256];
__device__ float g_pM[640 * 64];
__device__ float g_pL[640 * 64];

// ---------------- helpers ----------------
__device__ __forceinline__ uint32_t smem_u32(const void* p) {
    return (uint32_t)__cvta_generic_to_shared(p);
}

__device__ __forceinline__ void mma16(float* c, uint32_t a0, uint32_t a1,
                                      uint32_t a2, uint32_t a3,
                                      uint32_t b0, uint32_t b1) {
    asm volatile(
        "mma.sync.aligned.m16n8k16.row.col.f32.bf16.bf16.f32 "
        "{%0,%1,%2,%3}, {%4,%5,%6,%7}, {%8,%9}, {%0,%1,%2,%3};"
        : "+f"(c[0]), "+f"(c[1]), "+f"(c[2]), "+f"(c[3])
        : "r"(a0), "r"(a1), "r"(a2), "r"(a3), "r"(b0), "r"(b1));
}

__device__ __forceinline__ void ldm_x4(uint32_t& r0, uint32_t& r1,
                                       uint32_t& r2, uint32_t& r3, uint32_t addr) {
    asm volatile("ldmatrix.sync.aligned.m8n8.x4.shared.b16 {%0,%1,%2,%3}, [%4];"
                 : "=r"(r0), "=r"(r1), "=r"(r2), "=r"(r3) : "r"(addr));
}

__device__ __forceinline__ void ldm_x4t(uint32_t& r0, uint32_t& r1,
                                        uint32_t& r2, uint32_t& r3, uint32_t addr) {
    asm volatile("ldmatrix.sync.aligned.m8n8.x4.trans.shared.b16 {%0,%1,%2,%3}, [%4];"
                 : "=r"(r0), "=r"(r1), "=r"(r2), "=r"(r3) : "r"(addr));
}

__device__ __forceinline__ void cpa16(void* dst, const void* src) {
    asm volatile("cp.async.cg.shared.global [%0], [%1], 16;"
                 :: "r"(smem_u32(dst)), "l"(src));
}
#define CP_COMMIT()  asm volatile("cp.async.commit_group;")
#define CP_WAIT(n)   asm volatile("cp.async.wait_group %0;" :: "n"(n) : "memory")

__device__ __forceinline__ uint32_t bf2u(__nv_bfloat162 h) {
    uint32_t u; *(__nv_bfloat162*)&u = h; return u;
}

__device__ __forceinline__ float gelu_exact(float x) {
    return 0.5f * x * (1.0f + erff(x * 0.70710678118654752440f));
}

// ---------------- weight bf16 pre-round ----------------
__global__ void convert_w(const float* __restrict__ wq, const float* __restrict__ wk,
                          const float* __restrict__ wv, const float* __restrict__ wo,
                          const float* __restrict__ w1, const float* __restrict__ w2,
                          __nv_bfloat16* __restrict__ dst) {
    size_t i = ((size_t)blockIdx.x * 256 + threadIdx.x) * 4;
    const float* src; size_t off = i;
    if      (i < 65536)  { src = wq; }
    else if (i < 131072) { src = wk; off = i - 65536; }
    else if (i < 196608) { src = wv; off = i - 131072; }
    else if (i < 262144) { src = wo; off = i - 196608; }
    else if (i < 524288) { src = w1; off = i - 262144; }
    else                 { src = w2; off = i - 524288; }
    float4 v = *(const float4*)(src + off);
    uint2 pk;
    pk.x = bf2u(__floats2bfloat162_rn(v.x, v.y));
    pk.y = bf2u(__floats2bfloat162_rn(v.z, v.w));
    *(uint2*)(dst + i) = pk;
}

// ---------------- RMSNorm (fp32 in, bf16 out), one warp per row ------------
__global__ void rmsnorm_kernel(const float* __restrict__ x,
                               const float* __restrict__ w,
                               __nv_bfloat16* __restrict__ out) {
    int row = blockIdx.x * 8 + (threadIdx.x >> 5);
    int lane = threadIdx.x & 31;
    const float* xr = x + (size_t)row * D + lane * 8;
    float4 a = *(const float4*)xr;
    float4 b = *(const float4*)(xr + 4);
    float ss = a.x*a.x + a.y*a.y + a.z*a.z + a.w*a.w
             + b.x*b.x + b.y*b.y + b.z*b.z + b.w*b.w;
    #pragma unroll
    for (int o = 16; o > 0; o >>= 1) ss += __shfl_xor_sync(0xffffffffu, ss, o);
    float r = rsqrtf(ss * (1.0f / D) + 1e-6f);
    float4 wa = *(const float4*)(w + lane * 8);
    float4 wb = *(const float4*)(w + lane * 8 + 4);
    uint4 pk;
    pk.x = bf2u(__floats2bfloat162_rn(a.x * r * wa.x, a.y * r * wa.y));
    pk.y = bf2u(__floats2bfloat162_rn(a.z * r * wa.z, a.w * r * wa.w));
    pk.z = bf2u(__floats2bfloat162_rn(b.x * r * wb.x, b.y * r * wb.y));
    pk.w = bf2u(__floats2bfloat162_rn(b.z * r * wb.z, b.w * r * wb.w));
    *(uint4*)(out + (size_t)row * D + lane * 8) = pk;
}

// ---------------- bf16 GEMM: C = A[M,K] @ W[N,K]^T + bias ------------------
// block 128x128, 128 threads (4 warps 2x2), warp tile 64x64, k-chunk 64,
// ldmatrix fragments, cp.async double buffer.
// EPI: 0 = bias -> bf16, 1 = bias+GELU -> bf16, 2 = bias+residual -> fp32
#define GST 72            // smem row stride in halves (144B; ldmatrix conflict-free)
#define GBUF (128 * GST)  // one tile: 9216 halves

template <int EPI>
__device__ __forceinline__ void
gemm_body(const __nv_bfloat16* __restrict__ A, const __nv_bfloat16* __restrict__ W,
          const float* __restrict__ bias, const float* __restrict__ res,
          void* __restrict__ Cv, int N, int K) {
    extern __shared__ __align__(16) __nv_bfloat16 smh[];   // 2 buf x (A + B) tiles
    const int tid = threadIdx.x, lane = tid & 31, wid = tid >> 5;
    const int wm = wid >> 1, wn = wid & 1;
    const int g = lane >> 2, t = lane & 3;
    const int bm = blockIdx.y * 128, bn = blockIdx.x * 128;

    float acc[4][8][4];
    #pragma unroll
    for (int mf = 0; mf < 4; mf++)
        #pragma unroll
        for (int nf = 0; nf < 8; nf++)
            #pragma unroll
            for (int q = 0; q < 4; q++) acc[mf][nf][q] = 0.f;

    #define GFILL(bufp, kt) do {                                              \
        __nv_bfloat16* sA_ = smh + (bufp) * (2 * GBUF);                       \
        __nv_bfloat16* sB_ = sA_ + GBUF;                                      \
        _Pragma("unroll")                                                     \
        for (int p = 0; p < 8; p++) {                                         \
            int i = tid + p * 128; int r = i >> 3; int c = (i & 7) * 8;       \
            cpa16(sA_ + r * GST + c, A + (size_t)(bm + r) * K + (kt) + c);    \
            cpa16(sB_ + r * GST + c, W + (size_t)(bn + r) * K + (kt) + c);    \
        }                                                                     \
        CP_COMMIT();                                                          \
    } while (0)

    // per-lane ldmatrix offsets (halves) within a tile
    const uint32_t aoff = (uint32_t)((wm * 64 + (lane & 15)) * GST + (lane >> 4) * 8) * 2;
    const uint32_t boff = (uint32_t)((wn * 64 + (lane & 7) + (lane >> 4) * 8) * GST
                                     + ((lane >> 3) & 1) * 8) * 2;
    const uint32_t sbase = smem_u32(smh);

    GFILL(0, 0);
    int buf = 0;
    for (int kt = 0; kt < K; kt += 64) {
        if (kt + 64 < K) { GFILL(buf ^ 1, kt + 64); CP_WAIT(1); }
        else             { CP_WAIT(0); }
        __syncthreads();
        const uint32_t sAa = sbase + (uint32_t)buf * (2 * GBUF * 2);
        const uint32_t sBa = sAa + GBUF * 2;
        #pragma unroll
        for (int ks = 0; ks < 4; ks++) {
            uint32_t a[4][4];
            #pragma unroll
            for (int mf = 0; mf < 4; mf++)
                ldm_x4(a[mf][0], a[mf][1], a[mf][2], a[mf][3],
                       sAa + aoff + (uint32_t)(mf * 16 * GST) * 2 + ks * 32);
            #pragma unroll
            for (int nb = 0; nb < 4; nb++) {
                uint32_t r0, r1, r2, r3;
                ldm_x4(r0, r1, r2, r3,
                       sBa + boff + (uint32_t)(nb * 16 * GST) * 2 + ks * 32);
                #pragma unroll
                for (int mf = 0; mf < 4; mf++) {
                    mma16(acc[mf][2 * nb],     a[mf][0], a[mf][1], a[mf][2], a[mf][3], r0, r1);
                    mma16(acc[mf][2 * nb + 1], a[mf][0], a[mf][1], a[mf][2], a[mf][3], r2, r3);
                }
            }
        }
        __syncthreads();
        buf ^= 1;
    }
    #undef GFILL

    #pragma unroll
    for (int mf = 0; mf < 4; mf++) {
        #pragma unroll
        for (int nf = 0; nf < 8; nf++) {
            int row0 = bm + wm * 64 + mf * 16 + g;
            int col = bn + wn * 64 + nf * 8 + 2 * t;
            float2 bv = *(const float2*)&bias[col];
            #pragma unroll
            for (int h = 0; h < 2; h++) {
                int row = row0 + h * 8;
                float ox = acc[mf][nf][h * 2 + 0] + bv.x;
                float oy = acc[mf][nf][h * 2 + 1] + bv.y;
                if (EPI == 1) { ox = gelu_exact(ox); oy = gelu_exact(oy); }
                if (EPI == 2) {
                    float2 r2 = *(const float2*)(res + (size_t)row * N + col);
                    float2 o = make_float2(ox + r2.x, oy + r2.y);
                    *(float2*)((float*)Cv + (size_t)row * N + col) = o;
                } else {
                    *(uint32_t*)((__nv_bfloat16*)Cv + (size_t)row * N + col) =
                        bf2u(__floats2bfloat162_rn(ox, oy));
                }
            }
        }
    }
}

template <int EPI>
__global__ void __launch_bounds__(128, 2)
gemm_bf16(const __nv_bfloat16* __restrict__ A, const __nv_bfloat16* __restrict__ W,
          const float* __restrict__ bias, const float* __restrict__ res,
          void* __restrict__ Cv, int N, int K) {
    gemm_body<EPI>(A, W, bias, res, Cv, N, K);
}

__global__ void __launch_bounds__(128, 2)
gemm_qkv(const __nv_bfloat16* __restrict__ A, const __nv_bfloat16* __restrict__ wb,
         const float* __restrict__ bq, const float* __restrict__ bk,
         const float* __restrict__ bv,
         __nv_bfloat16* __restrict__ q, __nv_bfloat16* __restrict__ k,
         __nv_bfloat16* __restrict__ v) {
    int z = blockIdx.z;
    const __nv_bfloat16* W = wb + (size_t)z * 65536;
    const float* bias = (z == 0) ? bq : ((z == 1) ? bk : bv);
    __nv_bfloat16* C = (z == 0) ? q : ((z == 1) ? k : v);
    gemm_body<0>(A, W, bias, nullptr, C, 256, 256);
}

// ---------------- split-KV flash attention (unchanged from R13) ------------
#define QKVS 264          // smem row stride in halves (528B)
#define PSH  72
#define KVC  16           // k-blocks per chunk

__global__ void __launch_bounds__(256, 2)
flash_tc(const __nv_bfloat16* __restrict__ Q, const __nv_bfloat16* __restrict__ Kg,
         const __nv_bfloat16* __restrict__ Vg, __nv_bfloat16* __restrict__ O,
         float* __restrict__ pO, float* __restrict__ pM, float* __restrict__ pL) {
    extern __shared__ __align__(16) __nv_bfloat16 smh[];
    __nv_bfloat16* sQ = smh;                 // 64 x 264
    __nv_bfloat16* sK = sQ + 64 * QKVS;      // 64 x 264 (reused for O staging)
    __nv_bfloat16* sV = sK + 64 * QKVS;      // 64 x 264
    __nv_bfloat16* sP = sV + 64 * QKVS;      // 64 x 72
    __shared__ float sRmax[128], sRsum[128], sSc[64], sL[64];

    const int tid = threadIdx.x, lane = tid & 31, wid = tid >> 5;
    const int wm = wid >> 1, wn = wid & 1;
    const int g = lane >> 2, t = lane & 3;
    const int rA = wm * 16 + g, rB = rA + 8;

    const int id = blockIdx.x;
    int qblk, b, c, nc;
    if (id < 256)      { nc = 4; qblk = 63 - (id >> 4); int r = id & 15; b = r >> 2; c = r & 3; }
    else if (id < 448) { nc = 3; int u = id - 256; qblk = 47 - u / 12; int r = u % 12; b = r / 3; c = r % 3; }
    else if (id < 576) { nc = 2; int u = id - 448; qblk = 31 - (u >> 3); int r = u & 7; b = r >> 1; c = r & 1; }
    else               { nc = 1; int u = id - 576; qblk = 15 - (u >> 2); b = u & 3; c = 0; }
    const int j0 = c * KVC;
    const int j1 = min(j0 + KVC, qblk + 1);

    const size_t qbase = ((size_t)b * TT + (size_t)qblk * 64) * D;
    const size_t bbase = (size_t)b * TT * D;

    #pragma unroll
    for (int p = 0; p < 8; p++) {
        int i = tid + p * 256;
        int row = i >> 5, cv = i & 31;
        cpa16(sQ + row * QKVS + cv * 8, Q + qbase + (size_t)row * D + cv * 8);
        cpa16(sK + row * QKVS + cv * 8,
              Kg + bbase + (size_t)j0 * 64 * D + (size_t)row * D + cv * 8);
    }
    CP_COMMIT();

    const uint32_t sQa = smem_u32(sQ);
    const uint32_t sKa = smem_u32(sK);
    const uint32_t sVa = smem_u32(sV);
    const uint32_t sPa = smem_u32(sP);
    const uint32_t qaddr = sQa + (uint32_t)((wm * 16 + (lane & 15)) * QKVS
                                            + (lane >> 4) * 8) * 2;
    const uint32_t kaddr = sKa + (uint32_t)((wn * 32 + (lane & 7) + (lane >> 4) * 8) * QKVS
                                            + ((lane >> 3) & 1) * 8) * 2;
    const uint32_t paddr = sPa + (uint32_t)((wn * 32 + (lane & 7) + (lane >> 4) * 8) * PSH
                                            + ((lane >> 3) & 1) * 8) * 2;
    const uint32_t vaddr = sVa + (uint32_t)((((lane >> 4) & 1) * 8 + (lane & 7)) * QKVS
                                            + wm * 64 + ((lane >> 3) & 1) * 8) * 2;

    float oacc[4][4][4];
    #pragma unroll
    for (int mf = 0; mf < 4; mf++)
        #pragma unroll
        for (int nf = 0; nf < 4; nf++)
            #pragma unroll
            for (int q = 0; q < 4; q++) oacc[mf][nf][q] = 0.f;

    float mA = -1e30f, mB = -1e30f, lA = 0.f, lB = 0.f;

    for (int j = j0; j < j1; j++) {
        __syncthreads();
        {
            const __nv_bfloat16* vsrc = Vg + bbase + (size_t)j * 64 * D;
            #pragma unroll
            for (int p = 0; p < 8; p++) {
                int i = tid + p * 256;
                int row = i >> 5, cv = i & 31;
                cpa16(sV + row * QKVS + cv * 8, vsrc + (size_t)row * D + cv * 8);
            }
            CP_COMMIT();
        }
        CP_WAIT(1);
        __syncthreads();

        float s4[4][4];
        #pragma unroll
        for (int nf = 0; nf < 4; nf++)
            #pragma unroll
            for (int q = 0; q < 4; q++) s4[nf][q] = 0.f;

        #pragma unroll
        for (int ks = 0; ks < 16; ks++) {
            uint32_t qa0, qa1, qa2, qa3;
            ldm_x4(qa0, qa1, qa2, qa3, qaddr + ks * 32);
            #pragma unroll
            for (int np = 0; np < 2; np++) {
                uint32_t r0, r1, r2, r3;
                ldm_x4(r0, r1, r2, r3,
                       kaddr + (uint32_t)(np * 16 * QKVS) * 2 + ks * 32);
                mma16(s4[2 * np],     qa0, qa1, qa2, qa3, r0, r1);
                mma16(s4[2 * np + 1], qa0, qa1, qa2, qa3, r2, r3);
            }
        }

        if (j == qblk) {
            #pragma unroll
            for (int nf = 0; nf < 4; nf++) {
                int c0 = wn * 32 + nf * 8 + 2 * t;
                if (c0 > rA)     s4[nf][0] = -1e30f;
                if (c0 + 1 > rA) s4[nf][1] = -1e30f;
                if (c0 > rB)     s4[nf][2] = -1e30f;
                if (c0 + 1 > rB) s4[nf][3] = -1e30f;
            }
        }

        float mxA = -1e30f, mxB = -1e30f;
        #pragma unroll
        for (int nf = 0; nf < 4; nf++) {
            mxA = fmaxf(mxA, fmaxf(s4[nf][0], s4[nf][1]));
            mxB = fmaxf(mxB, fmaxf(s4[nf][2], s4[nf][3]));
        }
        mxA = fmaxf(mxA, __shfl_xor_sync(0xffffffffu, mxA, 1));
        mxA = fmaxf(mxA, __shfl_xor_sync(0xffffffffu, mxA, 2));
        mxB = fmaxf(mxB, __shfl_xor_sync(0xffffffffu, mxB, 1));
        mxB = fmaxf(mxB, __shfl_xor_sync(0xffffffffu, mxB, 2));
        const float msA = mxA * 0.0625f, msB = mxB * 0.0625f;

        float sumA = 0.f, sumB = 0.f;
        #pragma unroll
        for (int nf = 0; nf < 4; nf++) {
            float p0 = __expf(fmaf(s4[nf][0], 0.0625f, -msA));
            float p1 = __expf(fmaf(s4[nf][1], 0.0625f, -msA));
            float p2 = __expf(fmaf(s4[nf][2], 0.0625f, -msB));
            float p3 = __expf(fmaf(s4[nf][3], 0.0625f, -msB));
            s4[nf][0] = p0; s4[nf][1] = p1; s4[nf][2] = p2; s4[nf][3] = p3;
            sumA += p0 + p1; sumB += p2 + p3;
        }
        sumA += __shfl_xor_sync(0xffffffffu, sumA, 1);
        sumA += __shfl_xor_sync(0xffffffffu, sumA, 2);
        sumB += __shfl_xor_sync(0xffffffffu, sumB, 1);
        sumB += __shfl_xor_sync(0xffffffffu, sumB, 2);
        if (t == 0) {
            sRmax[wn * 64 + rA] = msA; sRmax[wn * 64 + rB] = msB;
            sRsum[wn * 64 + rA] = sumA; sRsum[wn * 64 + rB] = sumB;
        }
        __syncthreads();

        if (j < j1 - 1) {
            const __nv_bfloat16* ksrc = Kg + bbase + (size_t)(j + 1) * 64 * D;
            #pragma unroll
            for (int p = 0; p < 8; p++) {
                int i = tid + p * 256;
                int row = i >> 5, cv = i & 31;
                cpa16(sK + row * QKVS + cv * 8, ksrc + (size_t)row * D + cv * 8);
            }
            CP_COMMIT();
        }

        float m0 = sRmax[rA], m1 = sRmax[64 + rA];
        float nmA = fmaxf(mA, fmaxf(m0, m1));
        float scA = __expf(mA - nmA);
        lA = lA * scA + sRsum[rA] * __expf(m0 - nmA)
                      + sRsum[64 + rA] * __expf(m1 - nmA);
        float cfA = __expf(msA - nmA);
        mA = nmA;

        m0 = sRmax[rB]; m1 = sRmax[64 + rB];
        float nmB = fmaxf(mB, fmaxf(m0, m1));
        float scB = __expf(mB - nmB);
        lB = lB * scB + sRsum[rB] * __expf(m0 - nmB)
                      + sRsum[64 + rB] * __expf(m1 - nmB);
        float cfB = __expf(msB - nmB);
        mB = nmB;

        if (wn == 0 && t == 0) { sSc[rA] = scA; sSc[rB] = scB; }

        #pragma unroll
        for (int nf = 0; nf < 4; nf++) {
            int c0 = wn * 32 + nf * 8 + 2 * t;
            *(uint32_t*)(sP + rA * PSH + c0) =
                bf2u(__floats2bfloat162_rn(s4[nf][0] * cfA, s4[nf][1] * cfA));
            *(uint32_t*)(sP + rB * PSH + c0) =
                bf2u(__floats2bfloat162_rn(s4[nf][2] * cfB, s4[nf][3] * cfB));
        }

        if (j < j1 - 1) CP_WAIT(1); else CP_WAIT(0);
        __syncthreads();

        float scr[4][2];
        bool uni = true;
        #pragma unroll
        for (int nf = 0; nf < 4; nf++) {
            int qc = wn * 32 + nf * 8 + 2 * t;
            scr[nf][0] = sSc[qc]; scr[nf][1] = sSc[qc + 1];
            uni = uni && (scr[nf][0] == 1.f) && (scr[nf][1] == 1.f);
        }
        if (!__all_sync(0xffffffffu, uni)) {
            #pragma unroll
            for (int nf = 0; nf < 4; nf++)
                #pragma unroll
                for (int mf = 0; mf < 4; mf++) {
                    oacc[mf][nf][0] *= scr[nf][0]; oacc[mf][nf][1] *= scr[nf][1];
                    oacc[mf][nf][2] *= scr[nf][0]; oacc[mf][nf][3] *= scr[nf][1];
                }
        }

        #pragma unroll
        for (int sc = 0; sc < 4; sc++) {
            uint32_t bb[4][2];
            #pragma unroll
            for (int nq = 0; nq < 2; nq++)
                ldm_x4(bb[2 * nq][0], bb[2 * nq][1], bb[2 * nq + 1][0], bb[2 * nq + 1][1],
                       paddr + (uint32_t)(nq * 16 * PSH) * 2 + sc * 32);
            #pragma unroll
            for (int mf = 0; mf < 4; mf++) {
                uint32_t a0, a1, a2, a3;
                ldm_x4t(a0, a1, a2, a3,
                        vaddr + (uint32_t)(sc * 16 * QKVS + mf * 16) * 2);
                #pragma unroll
                for (int nf = 0; nf < 4; nf++)
                    mma16(oacc[mf][nf], a0, a1, a2, a3, bb[nf][0], bb[nf][1]);
            }
        }
    }

    __syncthreads();
    if (nc == 1) {
        if (wn == 0 && t == 0) { sL[rA] = lA; sL[rB] = lB; }
        __syncthreads();
        __nv_bfloat16* sO = sK;
        #pragma unroll
        for (int nf = 0; nf < 4; nf++) {
            int qc = wn * 32 + nf * 8 + 2 * t;
            float inv0 = 1.0f / sL[qc], inv1 = 1.0f / sL[qc + 1];
            #pragma unroll
            for (int mf = 0; mf < 4; mf++) {
                int dl = wm * 64 + mf * 16 + g;
                sO[qc * QKVS + dl]           = __float2bfloat16(oacc[mf][nf][0] * inv0);
                sO[(qc + 1) * QKVS + dl]     = __float2bfloat16(oacc[mf][nf][1] * inv1);
                sO[qc * QKVS + dl + 8]       = __float2bfloat16(oacc[mf][nf][2] * inv0);
                sO[(qc + 1) * QKVS + dl + 8] = __float2bfloat16(oacc[mf][nf][3] * inv1);
            }
        }
        __syncthreads();
        #pragma unroll
        for (int p = 0; p < 8; p++) {
            int i = tid + p * 256;
            int row = i >> 5, cv = i & 31;
            *(uint4*)(O + qbase + (size_t)row * D + cv * 8) =
                *(const uint4*)(sO + row * QKVS + cv * 8);
        }
    } else {
        float* sOf = (float*)(smh + 64 * QKVS);    // 64 x 260 fp32 (over sK+sV)
        #pragma unroll
        for (int nf = 0; nf < 4; nf++) {
            int qc = wn * 32 + nf * 8 + 2 * t;
            #pragma unroll
            for (int mf = 0; mf < 4; mf++) {
                int dl = wm * 64 + mf * 16 + g;
                sOf[qc * 260 + dl]           = oacc[mf][nf][0];
                sOf[(qc + 1) * 260 + dl]     = oacc[mf][nf][1];
                sOf[qc * 260 + dl + 8]       = oacc[mf][nf][2];
                sOf[(qc + 1) * 260 + dl + 8] = oacc[mf][nf][3];
            }
        }
        if (wn == 0 && t == 0) {
            pM[id * 64 + rA] = mA; pM[id * 64 + rB] = mB;
            pL[id * 64 + rA] = lA; pL[id * 64 + rB] = lB;
        }
        __syncthreads();
        float* dst = pO + (size_t)id * 16384;
        #pragma unroll
        for (int p = 0; p < 16; p++) {
            int i = tid + p * 256;
            int row = i >> 6, c4 = (i & 63) * 4;
            *(float4*)(dst + (size_t)row * 256 + c4) =
                *(const float4*)&sOf[row * 260 + c4];
        }
    }
}

// ---------------- combine partials (q-blocks with nc >= 2) -----------------
__global__ void __launch_bounds__(256)
combine_kernel(const float* __restrict__ pO, const float* __restrict__ pM,
               const float* __restrict__ pL, __nv_bfloat16* __restrict__ O) {
    int qblk = 16 + (blockIdx.x >> 2);
    int b = blockIdx.x & 3;
    int nc = qblk / 16 + 1;
    int base;
    if      (qblk >= 48) base = (63 - qblk) * 16;
    else if (qblk >= 32) base = 256 + (47 - qblk) * 12;
    else                 base = 448 + (31 - qblk) * 8;

    int row = threadIdx.x >> 2;
    int cg = (threadIdx.x & 3) * 64;

    float macc = -1e30f, lacc = 0.f;
    float acc[64];
    #pragma unroll
    for (int i = 0; i < 64; i++) acc[i] = 0.f;

    for (int c = 0; c < nc; c++) {
        int u = base + b * nc + c;
        float mc = pM[u * 64 + row], lc = pL[u * 64 + row];
        float nm = fmaxf(macc, mc);
        float w0 = __expf(macc - nm), w1 = __expf(mc - nm);
        lacc = lacc * w0 + lc * w1;
        const float* src = pO + (size_t)u * 16384 + (size_t)row * 256 + cg;
        #pragma unroll
        for (int i = 0; i < 64; i += 4) {
            float4 v = *(const float4*)(src + i);
            acc[i + 0] = acc[i + 0] * w0 + v.x * w1;
            acc[i + 1] = acc[i + 1] * w0 + v.y * w1;
            acc[i + 2] = acc[i + 2] * w0 + v.z * w1;
            acc[i + 3] = acc[i + 3] * w0 + v.w * w1;
        }
        macc = nm;
    }

    float inv = 1.0f / lacc;
    __nv_bfloat16* dst = O + ((size_t)b * TT + (size_t)qblk * 64 + row) * 256 + cg;
    #pragma unroll
    for (int i = 0; i < 64; i += 8) {
        uint4 pk;
        pk.x = bf2u(__floats2bfloat162_rn(acc[i + 0] * inv, acc[i + 1] * inv));
        pk.y = bf2u(__floats2bfloat162_rn(acc[i + 2] * inv, acc[i + 3] * inv));
        pk.z = bf2u(__floats2bfloat162_rn(acc[i + 4] * inv, acc[i + 5] * inv));
        pk.w = bf2u(__floats2bfloat162_rn(acc[i + 6] * inv, acc[i + 7] * inv));
        *(uint4*)(dst + i) = pk;
    }
}

// ---------------- launch ----------------
extern "C" void kernel_launch(void* const* d_in, const int* in_sizes, int n_in,
                              void* d_out, int out_size) {
    const float* x   = (const float*)d_in[0];
    const float* anw = (const float*)d_in[1];
    const float* mnw = (const float*)d_in[2];
    const float* wq  = (const float*)d_in[3];
    const float* bq  = (const float*)d_in[4];
    const float* wk  = (const float*)d_in[5];
    const float* bk  = (const float*)d_in[6];
    const float* wv  = (const float*)d_in[7];
    const float* bv  = (const float*)d_in[8];
    const float* wo  = (const float*)d_in[9];
    const float* bo  = (const float*)d_in[10];
    const float* w1  = (const float*)d_in[11];
    const float* b1  = (const float*)d_in[12];
    const float* w2  = (const float*)d_in[13];
    const float* b2  = (const float*)d_in[14];
    float* out = (float*)d_out;

    __nv_bfloat16 *xn, *q, *k, *v, *attn, *hn, *h, *wb;
    float *pO, *pM, *pL;
    cudaGetSymbolAddress((void**)&xn,   g_xnb);
    cudaGetSymbolAddress((void**)&q,    g_qb);
    cudaGetSymbolAddress((void**)&k,    g_kb);
    cudaGetSymbolAddress((void**)&v,    g_vb);
    cudaGetSymbolAddress((void**)&attn, g_attnb);
    cudaGetSymbolAddress((void**)&hn,   g_hnb);
    cudaGetSymbolAddress((void**)&h,    g_hb);
    cudaGetSymbolAddress((void**)&wb,   g_wb);
    cudaGetSymbolAddress((void**)&pO,   g_pO);
    cudaGetSymbolAddress((void**)&pM,   g_pM);
    cudaGetSymbolAddress((void**)&pL,   g_pL);

    const int GEMM_SMEM  = 2 * 2 * GBUF * 2;                     // 73728
    const int FLASH_SMEM = (3 * 64 * QKVS + 64 * PSH) * 2;       // 110592
    cudaFuncSetAttribute(flash_tc, cudaFuncAttributeMaxDynamicSharedMemorySize, FLASH_SMEM);
    cudaFuncSetAttribute(gemm_bf16<1>, cudaFuncAttributeMaxDynamicSharedMemorySize, GEMM_SMEM);
    cudaFuncSetAttribute(gemm_bf16<2>, cudaFuncAttributeMaxDynamicSharedMemorySize, GEMM_SMEM);
    cudaFuncSetAttribute(gemm_qkv, cudaFuncAttributeMaxDynamicSharedMemorySize, GEMM_SMEM);

    // 0) round weights to bf16
    convert_w<<<768, 256>>>(wq, wk, wv, wo, w1, w2, wb);
    // 1) attn-norm -> bf16
    rmsnorm_kernel<<<BT / 8, 256>>>(x, anw, xn);
    // 2) fused q,k,v projections
    gemm_qkv<<<dim3(2, 128, 3), 128, GEMM_SMEM>>>(xn, wb, bq, bk, bv, q, k, v);
    // 3) causal attention: split-KV units + combine
    flash_tc<<<640, 256, FLASH_SMEM>>>(q, k, v, attn, pO, pM, pL);
    combine_kernel<<<192, 256>>>(pO, pM, pL, attn);
    // 4) output projection + residual (fp32 out)
    gemm_bf16<2><<<dim3(2, 128), 128, GEMM_SMEM>>>(attn, wb + 196608, bo, x, out, 256, 256);
    // 5) mlp-norm -> bf16
    rmsnorm_kernel<<<BT / 8, 256>>>(out, mnw, hn);
    // 6) mlp up + gelu -> bf16
    gemm_bf16<1><<<dim3(8, 128), 128, GEMM_SMEM>>>(hn, wb + 262144, b1, nullptr, h, 1024, 256);
    // 7) mlp down + residual (in-place on out)
    gemm_bf16<2><<<dim3(2, 128), 128, GEMM_SMEM>>>(h, wb + 524288, b2, out, out, 256, 1024);
}